// round 1
// baseline (speedup 1.0000x reference)
#include <cuda_runtime.h>
#include <cuda_bf16.h>
#include <math.h>

#define BB 2
#define CC 512
#define HW 4096
#define NGROUP 32
#define CPG 16
#define EPSV 1e-6f

// ---------------- scratch (static device globals; no allocs allowed) ----------------
__device__ float g_t[(size_t)BB * HW * CC];      // groupnormed, (b, n, c)
__device__ float g_q[(size_t)BB * HW * CC];
__device__ float g_k[(size_t)BB * HW * CC];
__device__ float g_v[(size_t)BB * HW * CC];
__device__ float g_s[(size_t)BB * HW * HW];      // attention scores / probs
__device__ float g_ao[(size_t)BB * HW * CC];     // attn @ V, (b, n, c)
__device__ float g_o2[(size_t)BB * HW * CC];     // proj output, (b, n, c)

// ---------------- 1: GroupNorm + transpose to (b, n, c) ----------------
__global__ void groupnorm_kernel(const float* __restrict__ x,
                                 const float* __restrict__ gamma,
                                 const float* __restrict__ beta) {
    const int b = blockIdx.x / NGROUP;
    const int g = blockIdx.x % NGROUP;
    const int c0 = g * CPG;
    const int tid = threadIdx.x;
    const int NEL = CPG * HW;  // 65536

    float s = 0.f, s2 = 0.f;
    for (int i = tid; i < NEL; i += 256) {
        int c = c0 + (i >> 12);
        int p = i & (HW - 1);
        float v = x[((size_t)b * CC + c) * HW + p];
        s += v; s2 += v * v;
    }
    __shared__ float rs[256], rs2[256];
    rs[tid] = s; rs2[tid] = s2;
    __syncthreads();
    for (int off = 128; off > 0; off >>= 1) {
        if (tid < off) { rs[tid] += rs[tid + off]; rs2[tid] += rs2[tid + off]; }
        __syncthreads();
    }
    __shared__ float sh_mean, sh_inv;
    if (tid == 0) {
        float mean = rs[0] / (float)NEL;
        float var = rs2[0] / (float)NEL - mean * mean;
        sh_mean = mean;
        sh_inv = rsqrtf(var + EPSV);
    }
    __syncthreads();
    float mean = sh_mean, inv = sh_inv;

    for (int i = tid; i < NEL; i += 256) {
        int c = c0 + (i >> 12);
        int p = i & (HW - 1);
        float v = x[((size_t)b * CC + c) * HW + p];
        float xn = (v - mean) * inv;
        g_t[((size_t)b * HW + p) * CC + c] = xn * gamma[c] + beta[c];
    }
}

// ---------------- GEMM: C[m,n] = alpha * sum_k A[m,k] * B[n,k] + bias[n] ----------------
// A: M x K row-major, B: N x K row-major. Tiles 128x64x16, 256 threads, 8x4/thread.
__global__ void gemm_tn(const float* __restrict__ A, const float* __restrict__ Bm,
                        const float* __restrict__ bias, float* __restrict__ Cm,
                        int M, int N, int K,
                        long sA, long sB, long sC, float alpha) {
    A += (size_t)blockIdx.z * sA;
    Bm += (size_t)blockIdx.z * sB;
    Cm += (size_t)blockIdx.z * sC;
    const int bm = blockIdx.y * 128;
    const int bn = blockIdx.x * 64;
    const int tid = threadIdx.x;
    const int tx = tid & 15, ty = tid >> 4;

    __shared__ float As[16][128 + 4];
    __shared__ float Bs[16][64 + 4];

    float acc[8][4];
#pragma unroll
    for (int i = 0; i < 8; i++)
#pragma unroll
        for (int j = 0; j < 4; j++) acc[i][j] = 0.f;

    for (int k0 = 0; k0 < K; k0 += 16) {
#pragma unroll
        for (int l = 0; l < 8; l++) {
            int idx = tid + l * 256;
            int r = idx >> 4, c = idx & 15;
            As[c][r] = A[(size_t)(bm + r) * K + k0 + c];
        }
#pragma unroll
        for (int l = 0; l < 4; l++) {
            int idx = tid + l * 256;
            int r = idx >> 4, c = idx & 15;
            Bs[c][r] = Bm[(size_t)(bn + r) * K + k0 + c];
        }
        __syncthreads();
#pragma unroll
        for (int kk = 0; kk < 16; kk++) {
            float ra[8], rb[4];
#pragma unroll
            for (int i = 0; i < 8; i++) ra[i] = As[kk][ty * 8 + i];
#pragma unroll
            for (int j = 0; j < 4; j++) rb[j] = Bs[kk][tx * 4 + j];
#pragma unroll
            for (int i = 0; i < 8; i++)
#pragma unroll
                for (int j = 0; j < 4; j++) acc[i][j] += ra[i] * rb[j];
        }
        __syncthreads();
    }
#pragma unroll
    for (int i = 0; i < 8; i++) {
        int m = bm + ty * 8 + i;
#pragma unroll
        for (int j = 0; j < 4; j++) {
            int n = bn + tx * 4 + j;
            float v = acc[i][j] * alpha;
            if (bias) v += bias[n];
            Cm[(size_t)m * N + n] = v;
        }
    }
}

// ---------------- GEMM: C[m,n] = sum_k A[m,k] * B[k,n] ----------------
// A: M x K row-major, B: K x N row-major.
__global__ void gemm_nn(const float* __restrict__ A, const float* __restrict__ Bm,
                        float* __restrict__ Cm,
                        int M, int N, int K,
                        long sA, long sB, long sC) {
    A += (size_t)blockIdx.z * sA;
    Bm += (size_t)blockIdx.z * sB;
    Cm += (size_t)blockIdx.z * sC;
    const int bm = blockIdx.y * 128;
    const int bn = blockIdx.x * 64;
    const int tid = threadIdx.x;
    const int tx = tid & 15, ty = tid >> 4;

    __shared__ float As[16][128 + 4];
    __shared__ float Bs[16][64 + 4];

    float acc[8][4];
#pragma unroll
    for (int i = 0; i < 8; i++)
#pragma unroll
        for (int j = 0; j < 4; j++) acc[i][j] = 0.f;

    for (int k0 = 0; k0 < K; k0 += 16) {
#pragma unroll
        for (int l = 0; l < 8; l++) {
            int idx = tid + l * 256;
            int r = idx >> 4, c = idx & 15;
            As[c][r] = A[(size_t)(bm + r) * K + k0 + c];
        }
#pragma unroll
        for (int l = 0; l < 4; l++) {
            int idx = tid + l * 256;
            int r = idx >> 6, c = idx & 63;  // r: k, c: n
            Bs[r][c] = Bm[(size_t)(k0 + r) * N + bn + c];
        }
        __syncthreads();
#pragma unroll
        for (int kk = 0; kk < 16; kk++) {
            float ra[8], rb[4];
#pragma unroll
            for (int i = 0; i < 8; i++) ra[i] = As[kk][ty * 8 + i];
#pragma unroll
            for (int j = 0; j < 4; j++) rb[j] = Bs[kk][tx * 4 + j];
#pragma unroll
            for (int i = 0; i < 8; i++)
#pragma unroll
                for (int j = 0; j < 4; j++) acc[i][j] += ra[i] * rb[j];
        }
        __syncthreads();
    }
#pragma unroll
    for (int i = 0; i < 8; i++) {
        int m = bm + ty * 8 + i;
#pragma unroll
        for (int j = 0; j < 4; j++) {
            int n = bn + tx * 4 + j;
            Cm[(size_t)m * N + n] = acc[i][j];
        }
    }
}

// ---------------- softmax over rows of g_s (row length 4096) ----------------
__global__ void softmax_rows() {
    float* srow = g_s + (size_t)blockIdx.x * HW;
    const int tid = threadIdx.x;
    __shared__ float buf[HW];
    __shared__ float red[256];

    float mx = -INFINITY;
    for (int i = tid; i < HW; i += 256) {
        float v = srow[i];
        buf[i] = v;
        mx = fmaxf(mx, v);
    }
    red[tid] = mx;
    __syncthreads();
    for (int off = 128; off > 0; off >>= 1) {
        if (tid < off) red[tid] = fmaxf(red[tid], red[tid + off]);
        __syncthreads();
    }
    float rowmax = red[0];
    __syncthreads();

    float sum = 0.f;
    for (int i = tid; i < HW; i += 256) {
        float e = __expf(buf[i] - rowmax);
        buf[i] = e;
        sum += e;
    }
    red[tid] = sum;
    __syncthreads();
    for (int off = 128; off > 0; off >>= 1) {
        if (tid < off) red[tid] += red[tid + off];
        __syncthreads();
    }
    float inv = 1.f / red[0];
    __syncthreads();
    for (int i = tid; i < HW; i += 256) srow[i] = buf[i] * inv;
}

// ---------------- transpose (b,n,c)->(b,c,n) + residual add ----------------
__global__ void add_transpose(const float* __restrict__ x, float* __restrict__ out) {
    const int b = blockIdx.z;
    const int p0 = blockIdx.x * 32;
    const int c0 = blockIdx.y * 32;
    __shared__ float tile[32][33];
    const int tx = threadIdx.x, ty = threadIdx.y;
#pragma unroll
    for (int l = 0; l < 4; l++) {
        int p = p0 + ty + l * 8;
        tile[ty + l * 8][tx] = g_o2[((size_t)b * HW + p) * CC + c0 + tx];
    }
    __syncthreads();
#pragma unroll
    for (int l = 0; l < 4; l++) {
        int c = c0 + ty + l * 8;
        size_t idx = ((size_t)b * CC + c) * HW + p0 + tx;
        out[idx] = x[idx] + tile[tx][ty + l * 8];
    }
}

// ---------------- host launch ----------------
extern "C" void kernel_launch(void* const* d_in, const int* in_sizes, int n_in,
                              void* d_out, int out_size) {
    const float* x     = (const float*)d_in[0];
    const float* gamma = (const float*)d_in[1];
    const float* beta  = (const float*)d_in[2];
    const float* wq    = (const float*)d_in[3];
    const float* bq    = (const float*)d_in[4];
    const float* wk    = (const float*)d_in[5];
    const float* bk    = (const float*)d_in[6];
    const float* wv    = (const float*)d_in[7];
    const float* bv    = (const float*)d_in[8];
    const float* wp    = (const float*)d_in[9];
    const float* bp    = (const float*)d_in[10];
    float* out = (float*)d_out;

    float *pt, *pq, *pk, *pv, *ps, *pao, *po2;
    cudaGetSymbolAddress((void**)&pt,  g_t);
    cudaGetSymbolAddress((void**)&pq,  g_q);
    cudaGetSymbolAddress((void**)&pk,  g_k);
    cudaGetSymbolAddress((void**)&pv,  g_v);
    cudaGetSymbolAddress((void**)&ps,  g_s);
    cudaGetSymbolAddress((void**)&pao, g_ao);
    cudaGetSymbolAddress((void**)&po2, g_o2);

    const float scale = 0.044194173824159216f;  // 512^-0.5
    const int Mtok = BB * HW;                   // 8192

    // 1) GroupNorm + transpose
    groupnorm_kernel<<<BB * NGROUP, 256>>>(x, gamma, beta);

    // 2) Q, K, V projections
    {
        dim3 grid(CC / 64, Mtok / 128, 1);
        gemm_tn<<<grid, 256>>>(pt, wq, bq, pq, Mtok, CC, CC, 0, 0, 0, 1.f);
        gemm_tn<<<grid, 256>>>(pt, wk, bk, pk, Mtok, CC, CC, 0, 0, 0, 1.f);
        gemm_tn<<<grid, 256>>>(pt, wv, bv, pv, Mtok, CC, CC, 0, 0, 0, 1.f);
    }

    // 3) S = Q K^T * scale  (batched)
    {
        dim3 grid(HW / 64, HW / 128, BB);
        gemm_tn<<<grid, 256>>>(pq, pk, nullptr, ps, HW, HW, CC,
                               (long)HW * CC, (long)HW * CC, (long)HW * HW, scale);
    }

    // 4) softmax rows
    softmax_rows<<<BB * HW, 256>>>();

    // 5) O = P V (batched)
    {
        dim3 grid(CC / 64, HW / 128, BB);
        gemm_nn<<<grid, 256>>>(ps, pv, pao, HW, CC, HW,
                               (long)HW * HW, (long)HW * CC, (long)HW * CC);
    }

    // 6) proj
    {
        dim3 grid(CC / 64, Mtok / 128, 1);
        gemm_tn<<<grid, 256>>>(pao, wp, bp, po2, Mtok, CC, CC, 0, 0, 0, 1.f);
    }

    // 7) transpose + residual
    {
        dim3 grid(HW / 32, CC / 32, BB);
        add_transpose<<<grid, dim3(32, 8)>>>(x, out);
    }
}

// round 3
// speedup vs baseline: 2.8151x; 2.8151x over previous
#include <cuda_runtime.h>
#include <cuda_bf16.h>
#include <math.h>
#include <stdint.h>

#define BB 2
#define CC 512
#define HWN 4096
#define NGROUP 32
#define CPG 16
#define EPSV 1e-6f

typedef __nv_bfloat16 bf16;

// ---------------- scratch (static device globals; no allocs allowed) ----------------
__device__ bf16 g_th [(size_t)BB * HWN * CC];
__device__ bf16 g_tl [(size_t)BB * HWN * CC];
__device__ bf16 g_wh [(size_t)4 * CC * CC];
__device__ bf16 g_wl [(size_t)4 * CC * CC];
__device__ bf16 g_qh [(size_t)BB * HWN * CC];
__device__ bf16 g_ql [(size_t)BB * HWN * CC];
__device__ bf16 g_kh [(size_t)BB * HWN * CC];
__device__ bf16 g_kl [(size_t)BB * HWN * CC];
__device__ bf16 g_vth[(size_t)BB * CC * HWN];   // V transposed (b, c, n)
__device__ bf16 g_vtl[(size_t)BB * CC * HWN];
__device__ float g_s [(size_t)BB * HWN * HWN];  // fp32 scores
__device__ bf16 g_ph [(size_t)BB * HWN * HWN];  // softmax probs split
__device__ bf16 g_pl [(size_t)BB * HWN * HWN];
__device__ bf16 g_aoh[(size_t)BB * HWN * CC];
__device__ bf16 g_aol[(size_t)BB * HWN * CC];

// ================= helpers =================
__device__ __forceinline__ uint32_t smem_u32(const void* p) {
    uint32_t a;
    asm("{ .reg .u64 t; cvta.to.shared.u64 t, %1; cvt.u32.u64 %0, t; }" : "=r"(a) : "l"(p));
    return a;
}
#define CP16(dst, src) \
    asm volatile("cp.async.cg.shared.global [%0], [%1], 16;" :: "r"(dst), "l"(src))
#define CP_COMMIT() asm volatile("cp.async.commit_group;" ::: "memory")
#define CP_WAIT1()  asm volatile("cp.async.wait_group 1;" ::: "memory")

#define LDSM4(r, addr) \
    asm volatile("ldmatrix.sync.aligned.m8n8.x4.shared.b16 {%0,%1,%2,%3}, [%4];" \
        : "=r"((r)[0]), "=r"((r)[1]), "=r"((r)[2]), "=r"((r)[3]) : "r"(addr))

#define MMA_BF16(d, a, b) \
    asm volatile("mma.sync.aligned.m16n8k16.row.col.f32.bf16.bf16.f32 " \
        "{%0,%1,%2,%3}, {%4,%5,%6,%7}, {%8,%9}, {%0,%1,%2,%3};" \
        : "+f"((d)[0]), "+f"((d)[1]), "+f"((d)[2]), "+f"((d)[3]) \
        : "r"((a)[0]), "r"((a)[1]), "r"((a)[2]), "r"((a)[3]), "r"((b)[0]), "r"((b)[1]))

__device__ __forceinline__ uint32_t pack_bf2(float x, float y) {
    __nv_bfloat162 t = __floats2bfloat162_rn(x, y);
    return *(uint32_t*)&t;
}
__device__ __forceinline__ void split1(float v, bf16& h, bf16& l) {
    h = __float2bfloat16_rn(v);
    l = __float2bfloat16_rn(v - __bfloat162float(h));
}

// ================= split-bf16 HMMA GEMM =================
// C[m,n] = alpha * sum_k A[m,k]*B[n,k] (TN). A,B given as hi/lo bf16 pairs.
// mode 0: fp32 out Cf[m*ldc+n] * alpha
// mode 1: bf16 hi/lo out Ch/Cl[m*ldc+n] (+bias)
// mode 2: bf16 hi/lo out transposed: [((m>>12)*CC + n)*HWN + (m&4095)] (+bias)
// mode 3: fp32 out transposed + bias + residual
#define Bb_M 128
#define Bb_N 128
#define Bb_K 64
#define STG 65536  // bytes per smem stage (Ah,Al,Bh,Bl 16KB each)

__global__ void __launch_bounds__(256, 1)
gemm_mma(const bf16* __restrict__ Ah, const bf16* __restrict__ Al,
         const bf16* __restrict__ Bh, const bf16* __restrict__ Bl,
         const float* __restrict__ bias,
         float* __restrict__ Cf, bf16* __restrict__ Ch, bf16* __restrict__ Cl,
         const float* __restrict__ resid,
         int K, int lda, int ldb, int ldc,
         long sA, long sB, long sC, float alpha, int mode) {
    extern __shared__ __align__(1024) char smem[];
    const uint32_t sb32 = smem_u32(smem);
    const int tid = threadIdx.x;
    const int lane = tid & 31;
    const int wid = tid >> 5;
    const int wm = wid >> 2;          // 0..1
    const int wn = wid & 3;           // 0..3
    const long zz = blockIdx.z;

    Ah += zz * sA; Al += zz * sA;
    Bh += zz * sB; Bl += zz * sB;

    const int bm = blockIdx.y * Bb_M;
    const int bn = blockIdx.x * Bb_N;
    const int nck = K / Bb_K;

    // gmem -> smem stage loader (16B cp.async, swizzled dst)
    auto issue = [&](int ck, int st) {
        const int k0 = ck * Bb_K;
        const uint32_t sbase = sb32 + st * STG;
#pragma unroll
        for (int p = 0; p < 4; p++) {
            int idx = tid + p * 256;
            int r = idx >> 3;
            int c8 = idx & 7;
            uint32_t d = (uint32_t)(r * 128) + (uint32_t)((c8 * 16) ^ ((r & 7) << 4));
            const bf16* a_src = Ah + (size_t)(bm + r) * lda + k0 + c8 * 8;
            const bf16* al_src = Al + (size_t)(bm + r) * lda + k0 + c8 * 8;
            const bf16* b_src = Bh + (size_t)(bn + r) * ldb + k0 + c8 * 8;
            const bf16* bl_src = Bl + (size_t)(bn + r) * ldb + k0 + c8 * 8;
            CP16(sbase + d, a_src);
            CP16(sbase + 16384 + d, al_src);
            CP16(sbase + 32768 + d, b_src);
            CP16(sbase + 49152 + d, bl_src);
        }
        CP_COMMIT();
    };

    issue(0, 0);
    issue(1, 1);

    float acc[16][4];
#pragma unroll
    for (int i = 0; i < 16; i++)
#pragma unroll
        for (int j = 0; j < 4; j++) acc[i][j] = 0.f;

    // per-lane ldmatrix address components
    const int arow = wm * 64 + (lane & 7) + (lane & 8);        // + mf*16
    const uint32_t akx = ((lane >> 4) & 1) ? 16u : 0u;         // A k-half select
    const int brow = wn * 32 + (lane & 7) + ((lane >> 4) & 1) * 8;  // + nfp*16
    const uint32_t bkx = (lane & 8) ? 16u : 0u;                // B k-half select
    const uint32_t lxor = (uint32_t)((lane & 7) << 4);

    for (int ck = 0; ck < nck; ck++) {
        const int st = ck & 1;
        CP_WAIT1();
        __syncthreads();
        const uint32_t ab = sb32 + st * STG;

#pragma unroll
        for (int kk = 0; kk < 4; kk++) {
            const uint32_t kb = (uint32_t)(kk * 32);
            uint32_t ah[4][4], al[4][4];
#pragma unroll
            for (int mf = 0; mf < 4; mf++) {
                uint32_t ad = ab + (uint32_t)((arow + mf * 16) * 128) + ((kb + akx) ^ lxor);
                LDSM4(ah[mf], ad);
                LDSM4(al[mf], ad + 16384);
            }
            uint32_t bh[4][2], bl[4][2];
#pragma unroll
            for (int nfp = 0; nfp < 2; nfp++) {
                uint32_t bd = ab + 32768 + (uint32_t)((brow + nfp * 16) * 128) + ((kb + bkx) ^ lxor);
                uint32_t t[4];
                LDSM4(t, bd);
                bh[nfp * 2][0] = t[0]; bh[nfp * 2][1] = t[1];
                bh[nfp * 2 + 1][0] = t[2]; bh[nfp * 2 + 1][1] = t[3];
                LDSM4(t, bd + 16384);
                bl[nfp * 2][0] = t[0]; bl[nfp * 2][1] = t[1];
                bl[nfp * 2 + 1][0] = t[2]; bl[nfp * 2 + 1][1] = t[3];
            }
#pragma unroll
            for (int mf = 0; mf < 4; mf++)
#pragma unroll
                for (int nf = 0; nf < 4; nf++) {
                    MMA_BF16(acc[mf * 4 + nf], ah[mf], bh[nf]);
                    MMA_BF16(acc[mf * 4 + nf], ah[mf], bl[nf]);
                    MMA_BF16(acc[mf * 4 + nf], al[mf], bh[nf]);
                }
        }
        __syncthreads();
        if (ck + 2 < nck) issue(ck + 2, st);
        else CP_COMMIT();  // keep group count invariant
    }

    // ---------------- epilogue ----------------
    if (mode == 0) Cf += zz * sC;
    if (mode == 1) { Ch += zz * sC; Cl += zz * sC; }

#pragma unroll
    for (int mf = 0; mf < 4; mf++) {
#pragma unroll
        for (int nf = 0; nf < 4; nf++) {
            float* c = acc[mf * 4 + nf];
            const int m0 = bm + wm * 64 + mf * 16 + (lane >> 2);
            const int n0 = bn + wn * 32 + nf * 8 + 2 * (lane & 3);
#pragma unroll
            for (int half = 0; half < 2; half++) {
                const int m = m0 + half * 8;
                float v0 = c[half * 2 + 0];
                float v1 = c[half * 2 + 1];
                if (mode == 0) {
                    float2 o = make_float2(v0 * alpha, v1 * alpha);
                    *(float2*)(Cf + (size_t)m * ldc + n0) = o;
                } else if (mode == 1) {
                    if (bias) { v0 += bias[n0]; v1 += bias[n0 + 1]; }
                    float h0f = __bfloat162float(__float2bfloat16_rn(v0));
                    float h1f = __bfloat162float(__float2bfloat16_rn(v1));
                    uint32_t hp = pack_bf2(h0f, h1f);
                    uint32_t lp = pack_bf2(v0 - h0f, v1 - h1f);
                    size_t o = (size_t)m * ldc + n0;
                    *(uint32_t*)((char*)Ch + o * 2) = hp;
                    *(uint32_t*)((char*)Cl + o * 2) = lp;
                } else if (mode == 2) {
                    if (bias) { v0 += bias[n0]; v1 += bias[n0 + 1]; }
                    const int bb = m >> 12;
                    const int tok = m & (HWN - 1);
                    size_t o0 = ((size_t)bb * CC + n0) * HWN + tok;
                    bf16 h, l;
                    split1(v0, h, l); Ch[o0] = h; Cl[o0] = l;
                    split1(v1, h, l); Ch[o0 + HWN] = h; Cl[o0 + HWN] = l;
                } else {  // mode 3
                    const int bb = m >> 12;
                    const int tok = m & (HWN - 1);
                    size_t o0 = ((size_t)bb * CC + n0) * HWN + tok;
                    Cf[o0] = v0 + bias[n0] + resid[o0];
                    Cf[o0 + HWN] = v1 + bias[n0 + 1] + resid[o0 + HWN];
                }
            }
        }
    }
}

// ---------------- weight fp32 -> split bf16 ----------------
__global__ void convert_w(const float* __restrict__ w0, const float* __restrict__ w1,
                          const float* __restrict__ w2, const float* __restrict__ w3) {
    const float* w = (blockIdx.y == 0) ? w0 : (blockIdx.y == 1) ? w1
                   : (blockIdx.y == 2) ? w2 : w3;
    int i = blockIdx.x * 256 + threadIdx.x;
    float v = w[i];
    bf16 h, l;
    split1(v, h, l);
    size_t o = (size_t)blockIdx.y * (CC * CC) + i;
    g_wh[o] = h;
    g_wl[o] = l;
}

// ---------------- GroupNorm + transpose to (b, n, c), split bf16 ----------------
__global__ void groupnorm_kernel(const float* __restrict__ x,
                                 const float* __restrict__ gamma,
                                 const float* __restrict__ beta) {
    const int b = blockIdx.x / NGROUP;
    const int g = blockIdx.x % NGROUP;
    const int c0 = g * CPG;
    const int tid = threadIdx.x;
    const int NEL = CPG * HWN;

    float s = 0.f, s2 = 0.f;
    for (int i = tid; i < NEL; i += 256) {
        int c = c0 + (i >> 12);
        int p = i & (HWN - 1);
        float v = x[((size_t)b * CC + c) * HWN + p];
        s += v; s2 += v * v;
    }
    __shared__ float rs[256], rs2[256];
    rs[tid] = s; rs2[tid] = s2;
    __syncthreads();
    for (int off = 128; off > 0; off >>= 1) {
        if (tid < off) { rs[tid] += rs[tid + off]; rs2[tid] += rs2[tid + off]; }
        __syncthreads();
    }
    __shared__ float sh_mean, sh_inv;
    if (tid == 0) {
        float mean = rs[0] / (float)NEL;
        float var = rs2[0] / (float)NEL - mean * mean;
        sh_mean = mean;
        sh_inv = rsqrtf(var + EPSV);
    }
    __syncthreads();
    float mean = sh_mean, inv = sh_inv;
    for (int i = tid; i < NEL; i += 256) {
        int c = c0 + (i >> 12);
        int p = i & (HWN - 1);
        float v = x[((size_t)b * CC + c) * HWN + p];
        float t = (v - mean) * inv * gamma[c] + beta[c];
        size_t o = ((size_t)b * HWN + p) * CC + c;
        bf16 h, l;
        split1(t, h, l);
        g_th[o] = h;
        g_tl[o] = l;
    }
}

// ---------------- softmax rows of g_s -> split bf16 probs ----------------
__global__ void softmax_rows() {
    const size_t row = (size_t)blockIdx.x * HWN;
    const float* srow = g_s + row;
    const int tid = threadIdx.x;
    __shared__ float buf[HWN];
    __shared__ float red[256];

    float mx = -INFINITY;
    for (int i = tid; i < HWN; i += 256) {
        float v = srow[i];
        buf[i] = v;
        mx = fmaxf(mx, v);
    }
    red[tid] = mx;
    __syncthreads();
    for (int off = 128; off > 0; off >>= 1) {
        if (tid < off) red[tid] = fmaxf(red[tid], red[tid + off]);
        __syncthreads();
    }
    float rowmax = red[0];
    __syncthreads();

    float sum = 0.f;
    for (int i = tid; i < HWN; i += 256) {
        float e = __expf(buf[i] - rowmax);
        buf[i] = e;
        sum += e;
    }
    red[tid] = sum;
    __syncthreads();
    for (int off = 128; off > 0; off >>= 1) {
        if (tid < off) red[tid] += red[tid + off];
        __syncthreads();
    }
    float inv = 1.f / red[0];
    __syncthreads();
    for (int i = tid; i < HWN; i += 256) {
        float p = buf[i] * inv;
        bf16 h, l;
        split1(p, h, l);
        g_ph[row + i] = h;
        g_pl[row + i] = l;
    }
}

// ---------------- host launch ----------------
extern "C" void kernel_launch(void* const* d_in, const int* in_sizes, int n_in,
                              void* d_out, int out_size) {
    const float* x     = (const float*)d_in[0];
    const float* gamma = (const float*)d_in[1];
    const float* beta  = (const float*)d_in[2];
    const float* wq    = (const float*)d_in[3];
    const float* bq    = (const float*)d_in[4];
    const float* wk    = (const float*)d_in[5];
    const float* bk    = (const float*)d_in[6];
    const float* wv    = (const float*)d_in[7];
    const float* bv    = (const float*)d_in[8];
    const float* wp    = (const float*)d_in[9];
    const float* bp    = (const float*)d_in[10];
    float* out = (float*)d_out;

    bf16 *pth, *ptl, *pwh, *pwl, *pqh, *pql, *pkh, *pkl, *pvth, *pvtl, *pph, *ppl, *paoh, *paol;
    float* ps;
    cudaGetSymbolAddress((void**)&pth, g_th);
    cudaGetSymbolAddress((void**)&ptl, g_tl);
    cudaGetSymbolAddress((void**)&pwh, g_wh);
    cudaGetSymbolAddress((void**)&pwl, g_wl);
    cudaGetSymbolAddress((void**)&pqh, g_qh);
    cudaGetSymbolAddress((void**)&pql, g_ql);
    cudaGetSymbolAddress((void**)&pkh, g_kh);
    cudaGetSymbolAddress((void**)&pkl, g_kl);
    cudaGetSymbolAddress((void**)&pvth, g_vth);
    cudaGetSymbolAddress((void**)&pvtl, g_vtl);
    cudaGetSymbolAddress((void**)&pph, g_ph);
    cudaGetSymbolAddress((void**)&ppl, g_pl);
    cudaGetSymbolAddress((void**)&paoh, g_aoh);
    cudaGetSymbolAddress((void**)&paol, g_aol);
    cudaGetSymbolAddress((void**)&ps, g_s);

    const int DSMEM = 2 * STG;  // 128KB
    cudaFuncSetAttribute(gemm_mma, cudaFuncAttributeMaxDynamicSharedMemorySize, DSMEM);

    const float scale = 0.044194173824159216f;  // 512^-0.5
    const long SQC = (long)HWN * CC;            // 4096*512
    const long SQQ = (long)HWN * HWN;           // 4096*4096

    // 1) weight conversion + groupnorm
    convert_w<<<dim3(CC * CC / 256, 4), 256>>>(wq, wk, wv, wp);
    groupnorm_kernel<<<BB * NGROUP, 256>>>(x, gamma, beta);

    // 2) Q, K (mode 1), V transposed (mode 2)
    {
        dim3 grid(CC / Bb_N, BB * HWN / Bb_M, 1);
        gemm_mma<<<grid, 256, DSMEM>>>(pth, ptl, pwh + 0 * CC * CC, pwl + 0 * CC * CC,
                                       bq, nullptr, pqh, pql, nullptr,
                                       CC, CC, CC, CC, 0, 0, 0, 1.f, 1);
        gemm_mma<<<grid, 256, DSMEM>>>(pth, ptl, pwh + 1 * CC * CC, pwl + 1 * CC * CC,
                                       bk, nullptr, pkh, pkl, nullptr,
                                       CC, CC, CC, CC, 0, 0, 0, 1.f, 1);
        gemm_mma<<<grid, 256, DSMEM>>>(pth, ptl, pwh + 2 * CC * CC, pwl + 2 * CC * CC,
                                       bv, nullptr, pvth, pvtl, nullptr,
                                       CC, CC, CC, CC, 0, 0, 0, 1.f, 2);
    }

    // 3) S = Q K^T * scale (batched, fp32 out)
    {
        dim3 grid(HWN / Bb_N, HWN / Bb_M, BB);
        gemm_mma<<<grid, 256, DSMEM>>>(pqh, pql, pkh, pkl,
                                       nullptr, ps, nullptr, nullptr, nullptr,
                                       CC, CC, CC, HWN, SQC, SQC, SQQ, scale, 0);
    }

    // 4) softmax -> split probs
    softmax_rows<<<BB * HWN, 256>>>();

    // 5) O = P @ V  (B = V^T rows are channels, k = token)
    {
        dim3 grid(CC / Bb_N, HWN / Bb_M, BB);
        gemm_mma<<<grid, 256, DSMEM>>>(pph, ppl, pvth, pvtl,
                                       nullptr, nullptr, paoh, paol, nullptr,
                                       HWN, HWN, HWN, CC, SQQ, (long)CC * HWN, SQC, 1.f, 1);
    }

    // 6) proj + bias + residual, transposed store to (b, c, h, w)
    {
        dim3 grid(CC / Bb_N, BB * HWN / Bb_M, 1);
        gemm_mma<<<grid, 256, DSMEM>>>(paoh, paol, pwh + 3 * CC * CC, pwl + 3 * CC * CC,
                                       bp, out, nullptr, nullptr, x,
                                       CC, CC, CC, CC, 0, 0, 0, 1.f, 3);
    }
}

// round 4
// speedup vs baseline: 3.6759x; 1.3058x over previous
#include <cuda_runtime.h>
#include <cuda_fp16.h>
#include <math.h>
#include <stdint.h>

#define BB 2
#define CC 512
#define HWN 4096
#define NGROUP 32
#define CPG 16
#define EPSV 1e-6f

typedef __half half_t;

// ---------------- scratch (static device globals; no allocs allowed) ----------------
__device__ half_t g_th [(size_t)BB * HWN * CC];   // groupnormed hi (b,n,c)
__device__ half_t g_tl [(size_t)BB * HWN * CC];   // groupnormed lo
__device__ half_t g_wh [(size_t)3 * CC * CC];     // [wq;wk;wv] single fp16, rows = out-ch
__device__ half_t g_wph[(size_t)CC * CC];         // wp single fp16
__device__ float  g_bqkv[3 * CC];                 // [bq;bk;bv]
__device__ half_t g_qh [(size_t)BB * HWN * CC];   // Q hi
__device__ half_t g_ql [(size_t)BB * HWN * CC];   // Q lo
__device__ half_t g_kh [(size_t)BB * HWN * CC];   // K single
__device__ half_t g_vth[(size_t)BB * CC * HWN];   // V^T single (b,c,n)
__device__ float  g_s  [(size_t)BB * HWN * HWN];  // fp32 scores
__device__ half_t g_ph [(size_t)BB * HWN * HWN];  // probs hi
__device__ half_t g_pl [(size_t)BB * HWN * HWN];  // probs lo
__device__ half_t g_aoh[(size_t)BB * HWN * CC];   // attn@V hi
__device__ half_t g_aol[(size_t)BB * HWN * CC];   // attn@V lo

// ================= helpers =================
__device__ __forceinline__ uint32_t smem_u32(const void* p) {
    uint32_t a;
    asm("{ .reg .u64 t; cvta.to.shared.u64 t, %1; cvt.u32.u64 %0, t; }" : "=r"(a) : "l"(p));
    return a;
}
#define CP16(dst, src) \
    asm volatile("cp.async.cg.shared.global [%0], [%1], 16;" :: "r"(dst), "l"(src))
#define CP_COMMIT() asm volatile("cp.async.commit_group;" ::: "memory")
#define CP_WAIT1()  asm volatile("cp.async.wait_group 1;" ::: "memory")

#define LDSM4(r, addr) \
    asm volatile("ldmatrix.sync.aligned.m8n8.x4.shared.b16 {%0,%1,%2,%3}, [%4];" \
        : "=r"((r)[0]), "=r"((r)[1]), "=r"((r)[2]), "=r"((r)[3]) : "r"(addr))

#define MMA_F16(d, a, b) \
    asm volatile("mma.sync.aligned.m16n8k16.row.col.f32.f16.f16.f32 " \
        "{%0,%1,%2,%3}, {%4,%5,%6,%7}, {%8,%9}, {%0,%1,%2,%3};" \
        : "+f"((d)[0]), "+f"((d)[1]), "+f"((d)[2]), "+f"((d)[3]) \
        : "r"((a)[0]), "r"((a)[1]), "r"((a)[2]), "r"((a)[3]), "r"((b)[0]), "r"((b)[1]))

__device__ __forceinline__ void split1(float v, half_t& h, half_t& l) {
    h = __float2half_rn(v);
    l = __float2half_rn(v - __half2float(h));
}

// ================= 2-term split-fp16 HMMA GEMM =================
// C[m,n] = alpha * sum_k A[m,k]*B[n,k] (TN); A = Ah+Al (fp16 pair), B single fp16.
// mode 0: fp32 out Cf[m*ldc+n] * alpha (batched)
// mode 1: fp16 hi/lo out Ch/Cl[m*ldc+n] (+bias) (batched)
// mode 3: fp32 transposed + bias + residual (final output)
// mode 4: fused QKV routing: n<512 -> Ch/Cl (q split); <1024 -> C2 (k single);
//         else -> C3 (v single transposed)
#define Bb_M 128
#define Bb_N 128
#define Bb_K 64
#define STG 49152  // bytes per smem stage (Ah, Al, B : 16KB each)

__global__ void __launch_bounds__(256, 1)
gemm_mma(const half_t* __restrict__ Ah, const half_t* __restrict__ Al,
         const half_t* __restrict__ B,
         const float* __restrict__ bias,
         float* __restrict__ Cf, half_t* __restrict__ Ch, half_t* __restrict__ Cl,
         half_t* __restrict__ C2, half_t* __restrict__ C3,
         const float* __restrict__ resid,
         int K, int lda, int ldb, int ldc,
         long sA, long sB, long sC, float alpha, int mode) {
    extern __shared__ __align__(1024) char smem[];
    const uint32_t sb32 = smem_u32(smem);
    const int tid = threadIdx.x;
    const int lane = tid & 31;
    const int wid = tid >> 5;
    const int wm = wid >> 2;
    const int wn = wid & 3;
    const long zz = blockIdx.z;

    Ah += zz * sA; Al += zz * sA; B += zz * sB;

    const int bm = blockIdx.y * Bb_M;
    const int bn = blockIdx.x * Bb_N;
    const int nck = K / Bb_K;

    auto issue = [&](int ck) {
        const int st = ck % 3;
        const int k0 = ck * Bb_K;
        const uint32_t sbase = sb32 + st * STG;
#pragma unroll
        for (int p = 0; p < 4; p++) {
            int idx = tid + p * 256;
            int r = idx >> 3;
            int c8 = idx & 7;
            uint32_t d = (uint32_t)(r * 128) + (uint32_t)((c8 * 16) ^ ((r & 7) << 4));
            CP16(sbase + d,         Ah + (size_t)(bm + r) * lda + k0 + c8 * 8);
            CP16(sbase + 16384 + d, Al + (size_t)(bm + r) * lda + k0 + c8 * 8);
            CP16(sbase + 32768 + d, B  + (size_t)(bn + r) * ldb + k0 + c8 * 8);
        }
        CP_COMMIT();
    };

    issue(0);
    issue(1);

    float acc[16][4];
#pragma unroll
    for (int i = 0; i < 16; i++)
#pragma unroll
        for (int j = 0; j < 4; j++) acc[i][j] = 0.f;

    const int arow = wm * 64 + (lane & 7) + (lane & 8);
    const uint32_t akx = ((lane >> 4) & 1) ? 16u : 0u;
    const int brow = wn * 32 + (lane & 7) + ((lane >> 4) & 1) * 8;
    const uint32_t bkx = (lane & 8) ? 16u : 0u;
    const uint32_t lxor = (uint32_t)((lane & 7) << 4);

    for (int ck = 0; ck < nck; ck++) {
        CP_WAIT1();
        __syncthreads();
        if (ck + 2 < nck) issue(ck + 2);
        else CP_COMMIT();
        const uint32_t ab = sb32 + (uint32_t)((ck % 3) * STG);

#pragma unroll
        for (int kk = 0; kk < 4; kk++) {
            const uint32_t kb = (uint32_t)(kk * 32);
            uint32_t ah[4][4], al[4][4];
#pragma unroll
            for (int mf = 0; mf < 4; mf++) {
                uint32_t ad = ab + (uint32_t)((arow + mf * 16) * 128) + ((kb + akx) ^ lxor);
                LDSM4(ah[mf], ad);
                LDSM4(al[mf], ad + 16384);
            }
            uint32_t bh[4][2];
#pragma unroll
            for (int nfp = 0; nfp < 2; nfp++) {
                uint32_t bd = ab + 32768 + (uint32_t)((brow + nfp * 16) * 128) + ((kb + bkx) ^ lxor);
                uint32_t t[4];
                LDSM4(t, bd);
                bh[nfp * 2][0] = t[0]; bh[nfp * 2][1] = t[1];
                bh[nfp * 2 + 1][0] = t[2]; bh[nfp * 2 + 1][1] = t[3];
            }
#pragma unroll
            for (int mf = 0; mf < 4; mf++)
#pragma unroll
                for (int nf = 0; nf < 4; nf++) {
                    MMA_F16(acc[mf * 4 + nf], ah[mf], bh[nf]);
                    MMA_F16(acc[mf * 4 + nf], al[mf], bh[nf]);
                }
        }
    }

    // ---------------- epilogue ----------------
    if (mode == 0) Cf += zz * sC;
    if (mode == 1) { Ch += zz * sC; Cl += zz * sC; }

#pragma unroll
    for (int mf = 0; mf < 4; mf++) {
#pragma unroll
        for (int nf = 0; nf < 4; nf++) {
            float* c = acc[mf * 4 + nf];
            const int m0 = bm + wm * 64 + mf * 16 + (lane >> 2);
            const int n0 = bn + wn * 32 + nf * 8 + 2 * (lane & 3);
#pragma unroll
            for (int hf = 0; hf < 2; hf++) {
                const int m = m0 + hf * 8;
                float v0 = c[hf * 2 + 0];
                float v1 = c[hf * 2 + 1];
                if (mode == 0) {
                    *(float2*)(Cf + (size_t)m * ldc + n0) = make_float2(v0 * alpha, v1 * alpha);
                } else if (mode == 1) {
                    if (bias) { v0 += bias[n0]; v1 += bias[n0 + 1]; }
                    half_t h0, l0, h1, l1;
                    split1(v0, h0, l0);
                    split1(v1, h1, l1);
                    size_t o = (size_t)m * ldc + n0;
                    *(__half2*)(Ch + o) = __halves2half2(h0, h1);
                    *(__half2*)(Cl + o) = __halves2half2(l0, l1);
                } else if (mode == 4) {
                    v0 += bias[n0]; v1 += bias[n0 + 1];
                    const int seg = n0 >> 9;
                    const int nn = n0 & 511;
                    if (seg == 0) {
                        half_t h0, l0, h1, l1;
                        split1(v0, h0, l0);
                        split1(v1, h1, l1);
                        size_t o = (size_t)m * CC + nn;
                        *(__half2*)(Ch + o) = __halves2half2(h0, h1);
                        *(__half2*)(Cl + o) = __halves2half2(l0, l1);
                    } else if (seg == 1) {
                        size_t o = (size_t)m * CC + nn;
                        *(__half2*)(C2 + o) = __floats2half2_rn(v0, v1);
                    } else {
                        const int bb = m >> 12;
                        const int tok = m & (HWN - 1);
                        size_t o = ((size_t)bb * CC + nn) * HWN + tok;
                        C3[o] = __float2half_rn(v0);
                        C3[o + HWN] = __float2half_rn(v1);
                    }
                } else {  // mode 3
                    const int bb = m >> 12;
                    const int tok = m & (HWN - 1);
                    size_t o = ((size_t)bb * CC + n0) * HWN + tok;
                    Cf[o] = v0 + bias[n0] + resid[o];
                    Cf[o + HWN] = v1 + bias[n0 + 1] + resid[o + HWN];
                }
            }
        }
    }
}

// ---------------- weights fp32 -> fp16 single; bias concat ----------------
__global__ void convert_w(const float* __restrict__ w0, const float* __restrict__ w1,
                          const float* __restrict__ w2, const float* __restrict__ w3,
                          const float* __restrict__ b0, const float* __restrict__ b1,
                          const float* __restrict__ b2) {
    int i = blockIdx.x * 256 + threadIdx.x;
    int y = blockIdx.y;
    if (y < 3) {
        const float* w = (y == 0) ? w0 : (y == 1) ? w1 : w2;
        g_wh[(size_t)y * (CC * CC) + i] = __float2half_rn(w[i]);
        if (blockIdx.x < 2) {  // 512 threads handle biases
            int j = blockIdx.x * 256 + threadIdx.x;
            const float* b = (y == 0) ? b0 : (y == 1) ? b1 : b2;
            g_bqkv[y * CC + j] = b[j];
        }
    } else {
        g_wph[i] = __float2half_rn(w3[i]);
    }
}

// ---------------- GroupNorm + transpose to (b,n,c), split fp16 ----------------
__global__ void groupnorm_kernel(const float* __restrict__ x,
                                 const float* __restrict__ gamma,
                                 const float* __restrict__ beta) {
    const int b = blockIdx.x / NGROUP;
    const int g = blockIdx.x % NGROUP;
    const int c0 = g * CPG;
    const int tid = threadIdx.x;
    const int NEL = CPG * HWN;

    float s = 0.f, s2 = 0.f;
    for (int i = tid; i < NEL; i += 256) {
        int c = c0 + (i >> 12);
        int p = i & (HWN - 1);
        float v = x[((size_t)b * CC + c) * HWN + p];
        s += v; s2 += v * v;
    }
    __shared__ float rs[256], rs2[256];
    rs[tid] = s; rs2[tid] = s2;
    __syncthreads();
    for (int off = 128; off > 0; off >>= 1) {
        if (tid < off) { rs[tid] += rs[tid + off]; rs2[tid] += rs2[tid + off]; }
        __syncthreads();
    }
    __shared__ float sh_mean, sh_inv;
    if (tid == 0) {
        float mean = rs[0] / (float)NEL;
        float var = rs2[0] / (float)NEL - mean * mean;
        sh_mean = mean;
        sh_inv = rsqrtf(var + EPSV);
    }
    __syncthreads();
    float mean = sh_mean, inv = sh_inv;
    for (int i = tid; i < NEL; i += 256) {
        int c = c0 + (i >> 12);
        int p = i & (HWN - 1);
        float v = x[((size_t)b * CC + c) * HWN + p];
        float t = (v - mean) * inv * gamma[c] + beta[c];
        size_t o = ((size_t)b * HWN + p) * CC + c;
        half_t h, l;
        split1(t, h, l);
        g_th[o] = h;
        g_tl[o] = l;
    }
}

// ---------------- softmax rows of g_s -> split fp16 probs ----------------
__global__ void softmax_rows() {
    const size_t row = (size_t)blockIdx.x * HWN;
    const float* srow = g_s + row;
    const int tid = threadIdx.x;
    __shared__ float buf[HWN];
    __shared__ float red[256];

    float mx = -INFINITY;
    for (int i = tid * 4; i < HWN; i += 1024) {
        float4 v = *(const float4*)(srow + i);
        *(float4*)(buf + i) = v;
        mx = fmaxf(mx, fmaxf(fmaxf(v.x, v.y), fmaxf(v.z, v.w)));
    }
    red[tid] = mx;
    __syncthreads();
    for (int off = 128; off > 0; off >>= 1) {
        if (tid < off) red[tid] = fmaxf(red[tid], red[tid + off]);
        __syncthreads();
    }
    float rowmax = red[0];
    __syncthreads();

    float sum = 0.f;
    for (int i = tid; i < HWN; i += 256) {
        float e = __expf(buf[i] - rowmax);
        buf[i] = e;
        sum += e;
    }
    red[tid] = sum;
    __syncthreads();
    for (int off = 128; off > 0; off >>= 1) {
        if (tid < off) red[tid] += red[tid + off];
        __syncthreads();
    }
    float inv = 1.f / red[0];
    __syncthreads();
    for (int i = tid; i < HWN; i += 256) {
        float p = buf[i] * inv;
        half_t h, l;
        split1(p, h, l);
        g_ph[row + i] = h;
        g_pl[row + i] = l;
    }
}

// ---------------- host launch ----------------
extern "C" void kernel_launch(void* const* d_in, const int* in_sizes, int n_in,
                              void* d_out, int out_size) {
    const float* x     = (const float*)d_in[0];
    const float* gamma = (const float*)d_in[1];
    const float* beta  = (const float*)d_in[2];
    const float* wq    = (const float*)d_in[3];
    const float* bq    = (const float*)d_in[4];
    const float* wk    = (const float*)d_in[5];
    const float* bk    = (const float*)d_in[6];
    const float* wv    = (const float*)d_in[7];
    const float* bv    = (const float*)d_in[8];
    const float* wp    = (const float*)d_in[9];
    const float* bp    = (const float*)d_in[10];
    float* out = (float*)d_out;

    half_t *pth, *ptl, *pwh, *pwph, *pqh, *pql, *pkh, *pvth, *pph, *ppl, *paoh, *paol;
    float *ps, *pbqkv;
    cudaGetSymbolAddress((void**)&pth,  g_th);
    cudaGetSymbolAddress((void**)&ptl,  g_tl);
    cudaGetSymbolAddress((void**)&pwh,  g_wh);
    cudaGetSymbolAddress((void**)&pwph, g_wph);
    cudaGetSymbolAddress((void**)&pbqkv, g_bqkv);
    cudaGetSymbolAddress((void**)&pqh,  g_qh);
    cudaGetSymbolAddress((void**)&pql,  g_ql);
    cudaGetSymbolAddress((void**)&pkh,  g_kh);
    cudaGetSymbolAddress((void**)&pvth, g_vth);
    cudaGetSymbolAddress((void**)&pph,  g_ph);
    cudaGetSymbolAddress((void**)&ppl,  g_pl);
    cudaGetSymbolAddress((void**)&paoh, g_aoh);
    cudaGetSymbolAddress((void**)&paol, g_aol);
    cudaGetSymbolAddress((void**)&ps,   g_s);

    const int DSMEM = 3 * STG;  // 144KB
    cudaFuncSetAttribute(gemm_mma, cudaFuncAttributeMaxDynamicSharedMemorySize, DSMEM);

    const float scale = 0.044194173824159216f;  // 512^-0.5
    const long SQC = (long)HWN * CC;
    const long SQQ = (long)HWN * HWN;

    // 1) convert weights/bias + groupnorm (independent)
    convert_w<<<dim3(CC * CC / 256, 4), 256>>>(wq, wk, wv, wp, bq, bk, bv);
    groupnorm_kernel<<<BB * NGROUP, 256>>>(x, gamma, beta);

    // 2) fused QKV: N = 1536 over stacked weights
    {
        dim3 grid(3 * CC / Bb_N, BB * HWN / Bb_M, 1);
        gemm_mma<<<grid, 256, DSMEM>>>(pth, ptl, pwh, pbqkv,
                                       nullptr, pqh, pql, pkh, pvth, nullptr,
                                       CC, CC, CC, CC, 0, 0, 0, 1.f, 4);
    }

    // 3) S = Q K^T * scale (batched, fp32)
    {
        dim3 grid(HWN / Bb_N, HWN / Bb_M, BB);
        gemm_mma<<<grid, 256, DSMEM>>>(pqh, pql, pkh,
                                       nullptr, ps, nullptr, nullptr, nullptr, nullptr, nullptr,
                                       CC, CC, CC, HWN, SQC, SQC, SQQ, scale, 0);
    }

    // 4) softmax -> split probs
    softmax_rows<<<BB * HWN, 256>>>();

    // 5) O = P @ V (B = V^T, single fp16)
    {
        dim3 grid(CC / Bb_N, HWN / Bb_M, BB);
        gemm_mma<<<grid, 256, DSMEM>>>(pph, ppl, pvth,
                                       nullptr, nullptr, paoh, paol, nullptr, nullptr, nullptr,
                                       HWN, HWN, HWN, CC, SQQ, (long)CC * HWN, SQC, 1.f, 1);
    }

    // 6) proj + bias + residual, transposed store to (b,c,h,w)
    {
        dim3 grid(CC / Bb_N, BB * HWN / Bb_M, 1);
        gemm_mma<<<grid, 256, DSMEM>>>(paoh, paol, pwph,
                                       bp, out, nullptr, nullptr, nullptr, nullptr, x,
                                       CC, CC, CC, CC, 0, 0, 0, 1.f, 3);
    }
}

// round 5
// speedup vs baseline: 4.4120x; 1.2002x over previous
#include <cuda_runtime.h>
#include <cuda_fp16.h>
#include <math.h>
#include <stdint.h>

#define BB 2
#define CC 512
#define HWN 4096
#define NGROUP 32
#define CPG 16
#define EPSV 1e-6f

typedef __half half_t;

// ---------------- scratch (static device globals; no allocs allowed) ----------------
__device__ half_t g_th [(size_t)BB * HWN * CC];   // groupnormed hi (b,n,c)
__device__ half_t g_tl [(size_t)BB * HWN * CC];   // groupnormed lo
__device__ half_t g_wh [(size_t)3 * CC * CC];     // [wq;wk;wv] fp16, rows = out-ch
__device__ half_t g_wph[(size_t)CC * CC];         // wp fp16
__device__ float  g_bqkv[3 * CC];                 // [bq;bk;bv]
__device__ half_t g_qh [(size_t)BB * HWN * CC];   // Q hi
__device__ half_t g_ql [(size_t)BB * HWN * CC];   // Q lo
__device__ half_t g_kh [(size_t)BB * HWN * CC];   // K single
__device__ half_t g_vth[(size_t)BB * CC * HWN];   // V^T single (b,c,n)
__device__ half_t g_ph [(size_t)BB * HWN * HWN];  // unnormalized probs fp16
__device__ float  g_rsi[(size_t)BB * HWN];        // 1 / rowsum
__device__ half_t g_aoh[(size_t)BB * HWN * CC];   // attn@V hi
__device__ half_t g_aol[(size_t)BB * HWN * CC];   // attn@V lo

// ================= helpers =================
__device__ __forceinline__ uint32_t smem_u32(const void* p) {
    uint32_t a;
    asm("{ .reg .u64 t; cvta.to.shared.u64 t, %1; cvt.u32.u64 %0, t; }" : "=r"(a) : "l"(p));
    return a;
}
#define CP16(dst, src) \
    asm volatile("cp.async.cg.shared.global [%0], [%1], 16;" :: "r"(dst), "l"(src))
#define CP_COMMIT() asm volatile("cp.async.commit_group;" ::: "memory")
#define CP_WAIT1()  asm volatile("cp.async.wait_group 1;" ::: "memory")

#define LDSM4(r, addr) \
    asm volatile("ldmatrix.sync.aligned.m8n8.x4.shared.b16 {%0,%1,%2,%3}, [%4];" \
        : "=r"((r)[0]), "=r"((r)[1]), "=r"((r)[2]), "=r"((r)[3]) : "r"(addr))

#define MMA_F16(d, a, b) \
    asm volatile("mma.sync.aligned.m16n8k16.row.col.f32.f16.f16.f32 " \
        "{%0,%1,%2,%3}, {%4,%5,%6,%7}, {%8,%9}, {%0,%1,%2,%3};" \
        : "+f"((d)[0]), "+f"((d)[1]), "+f"((d)[2]), "+f"((d)[3]) \
        : "r"((a)[0]), "r"((a)[1]), "r"((a)[2]), "r"((a)[3]), "r"((b)[0]), "r"((b)[1]))

__device__ __forceinline__ void split1(float v, half_t& h, half_t& l) {
    h = __float2half_rn(v);
    l = __float2half_rn(v - __half2float(h));
}

// ================= 2-term split-fp16 HMMA GEMM =================
// C[m,n] = sum_k A[m,k]*B[n,k] (TN); A = Ah(+Al if SPLIT_A), B single fp16.
// MODE 3: fp32 transposed out + bias + residual (final output)
// MODE 4: fused QKV routing: n<512 -> q split; <1024 -> k single; else v^T single
// MODE 5: P = exp2(acc * alpha) stored fp16 (batched; softmax numerator)
// MODE 6: out = acc * extra[row] (inv rowsum), split fp16 store (batched)
#define Bb_M 128
#define Bb_N 128
#define Bb_K 64
#define STG 49152  // bytes per smem stage (Ah, Al, B : 16KB each)

template <int MODE, bool SPLIT_A>
__global__ void __launch_bounds__(256, 1)
gemm_mma(const half_t* __restrict__ Ah, const half_t* __restrict__ Al,
         const half_t* __restrict__ B,
         const float* __restrict__ bias,
         float* __restrict__ Cf, half_t* __restrict__ Ch, half_t* __restrict__ Cl,
         half_t* __restrict__ C2, half_t* __restrict__ C3,
         const float* __restrict__ extra,
         int K, int lda, int ldb, int ldc,
         long sA, long sB, long sC, float alpha) {
    extern __shared__ __align__(1024) char smem[];
    const uint32_t sb32 = smem_u32(smem);
    const int tid = threadIdx.x;
    const int lane = tid & 31;
    const int wid = tid >> 5;
    const int wm = wid >> 2;
    const int wn = wid & 3;
    const long zz = blockIdx.z;

    Ah += zz * sA;
    if (SPLIT_A) Al += zz * sA;
    B += zz * sB;

    const int bm = blockIdx.y * Bb_M;
    const int bn = blockIdx.x * Bb_N;
    const int nck = K / Bb_K;

    auto issue = [&](int ck) {
        const int st = ck % 3;
        const int k0 = ck * Bb_K;
        const uint32_t sbase = sb32 + st * STG;
#pragma unroll
        for (int p = 0; p < 4; p++) {
            int idx = tid + p * 256;
            int r = idx >> 3;
            int c8 = idx & 7;
            uint32_t d = (uint32_t)(r * 128) + (uint32_t)((c8 * 16) ^ ((r & 7) << 4));
            CP16(sbase + d, Ah + (size_t)(bm + r) * lda + k0 + c8 * 8);
            if (SPLIT_A)
                CP16(sbase + 16384 + d, Al + (size_t)(bm + r) * lda + k0 + c8 * 8);
            CP16(sbase + 32768 + d, B + (size_t)(bn + r) * ldb + k0 + c8 * 8);
        }
        CP_COMMIT();
    };

    issue(0);
    issue(1);

    float acc[16][4];
#pragma unroll
    for (int i = 0; i < 16; i++)
#pragma unroll
        for (int j = 0; j < 4; j++) acc[i][j] = 0.f;

    const int arow = wm * 64 + (lane & 7) + (lane & 8);
    const uint32_t akx = ((lane >> 4) & 1) ? 16u : 0u;
    const int brow = wn * 32 + (lane & 7) + ((lane >> 4) & 1) * 8;
    const uint32_t bkx = (lane & 8) ? 16u : 0u;
    const uint32_t lxor = (uint32_t)((lane & 7) << 4);

    for (int ck = 0; ck < nck; ck++) {
        CP_WAIT1();
        __syncthreads();
        if (ck + 2 < nck) issue(ck + 2);
        else CP_COMMIT();
        const uint32_t ab = sb32 + (uint32_t)((ck % 3) * STG);

#pragma unroll
        for (int kk = 0; kk < 4; kk++) {
            const uint32_t kb = (uint32_t)(kk * 32);
            uint32_t ah[4][4], al[4][4];
#pragma unroll
            for (int mf = 0; mf < 4; mf++) {
                uint32_t ad = ab + (uint32_t)((arow + mf * 16) * 128) + ((kb + akx) ^ lxor);
                LDSM4(ah[mf], ad);
                if (SPLIT_A) LDSM4(al[mf], ad + 16384);
            }
            uint32_t bh[4][2];
#pragma unroll
            for (int nfp = 0; nfp < 2; nfp++) {
                uint32_t bd = ab + 32768 + (uint32_t)((brow + nfp * 16) * 128) + ((kb + bkx) ^ lxor);
                uint32_t t[4];
                LDSM4(t, bd);
                bh[nfp * 2][0] = t[0]; bh[nfp * 2][1] = t[1];
                bh[nfp * 2 + 1][0] = t[2]; bh[nfp * 2 + 1][1] = t[3];
            }
#pragma unroll
            for (int mf = 0; mf < 4; mf++)
#pragma unroll
                for (int nf = 0; nf < 4; nf++) {
                    MMA_F16(acc[mf * 4 + nf], ah[mf], bh[nf]);
                    if (SPLIT_A) MMA_F16(acc[mf * 4 + nf], al[mf], bh[nf]);
                }
        }
    }

    // ---------------- epilogue ----------------
    if (MODE == 5) Ch += zz * sC;
    if (MODE == 6) { Ch += zz * sC; Cl += zz * sC; }

#pragma unroll
    for (int mf = 0; mf < 4; mf++) {
#pragma unroll
        for (int nf = 0; nf < 4; nf++) {
            float* c = acc[mf * 4 + nf];
            const int m0 = bm + wm * 64 + mf * 16 + (lane >> 2);
            const int n0 = bn + wn * 32 + nf * 8 + 2 * (lane & 3);
#pragma unroll
            for (int hf = 0; hf < 2; hf++) {
                const int m = m0 + hf * 8;
                float v0 = c[hf * 2 + 0];
                float v1 = c[hf * 2 + 1];
                if (MODE == 5) {
                    // x = acc * (scale*log2e); p = exp2(x), fp16x2 MUFU
                    __half2 x = __floats2half2_rn(v0 * alpha, v1 * alpha);
                    *(__half2*)(Ch + (size_t)m * ldc + n0) = h2exp2(x);
                } else if (MODE == 6) {
                    float inv = extra[zz * HWN + m];
                    v0 *= inv; v1 *= inv;
                    half_t h0, l0, h1, l1;
                    split1(v0, h0, l0);
                    split1(v1, h1, l1);
                    size_t o = (size_t)m * ldc + n0;
                    *(__half2*)(Ch + o) = __halves2half2(h0, h1);
                    *(__half2*)(Cl + o) = __halves2half2(l0, l1);
                } else if (MODE == 4) {
                    v0 += bias[n0]; v1 += bias[n0 + 1];
                    const int seg = n0 >> 9;
                    const int nn = n0 & 511;
                    if (seg == 0) {
                        half_t h0, l0, h1, l1;
                        split1(v0, h0, l0);
                        split1(v1, h1, l1);
                        size_t o = (size_t)m * CC + nn;
                        *(__half2*)(Ch + o) = __halves2half2(h0, h1);
                        *(__half2*)(Cl + o) = __halves2half2(l0, l1);
                    } else if (seg == 1) {
                        size_t o = (size_t)m * CC + nn;
                        *(__half2*)(C2 + o) = __floats2half2_rn(v0, v1);
                    } else {
                        const int bb = m >> 12;
                        const int tok = m & (HWN - 1);
                        size_t o = ((size_t)bb * CC + nn) * HWN + tok;
                        C3[o] = __float2half_rn(v0);
                        C3[o + HWN] = __float2half_rn(v1);
                    }
                } else {  // MODE 3: proj + bias + residual, transposed fp32
                    const int bb = m >> 12;
                    const int tok = m & (HWN - 1);
                    size_t o = ((size_t)bb * CC + n0) * HWN + tok;
                    Cf[o] = v0 + bias[n0] + extra[o];
                    Cf[o + HWN] = v1 + bias[n0 + 1] + extra[o + HWN];
                }
            }
        }
    }
}

// ---------------- weights fp32 -> fp16; bias concat ----------------
__global__ void convert_w(const float* __restrict__ w0, const float* __restrict__ w1,
                          const float* __restrict__ w2, const float* __restrict__ w3,
                          const float* __restrict__ b0, const float* __restrict__ b1,
                          const float* __restrict__ b2) {
    int i = blockIdx.x * 256 + threadIdx.x;
    int y = blockIdx.y;
    if (y < 3) {
        const float* w = (y == 0) ? w0 : (y == 1) ? w1 : w2;
        g_wh[(size_t)y * (CC * CC) + i] = __float2half_rn(w[i]);
        if (blockIdx.x < 2) {
            int j = blockIdx.x * 256 + threadIdx.x;
            const float* b = (y == 0) ? b0 : (y == 1) ? b1 : b2;
            g_bqkv[y * CC + j] = b[j];
        }
    } else {
        g_wph[i] = __float2half_rn(w3[i]);
    }
}

// ---------------- GroupNorm + transpose to (b,n,c), split fp16 ----------------
__global__ void groupnorm_kernel(const float* __restrict__ x,
                                 const float* __restrict__ gamma,
                                 const float* __restrict__ beta) {
    const int b = blockIdx.x / NGROUP;
    const int g = blockIdx.x % NGROUP;
    const int c0 = g * CPG;
    const int tid = threadIdx.x;
    const int NEL = CPG * HWN;

    float s = 0.f, s2 = 0.f;
    for (int i = tid; i < NEL; i += 256) {
        int c = c0 + (i >> 12);
        int p = i & (HWN - 1);
        float v = x[((size_t)b * CC + c) * HWN + p];
        s += v; s2 += v * v;
    }
    __shared__ float rs[256], rs2[256];
    rs[tid] = s; rs2[tid] = s2;
    __syncthreads();
    for (int off = 128; off > 0; off >>= 1) {
        if (tid < off) { rs[tid] += rs[tid + off]; rs2[tid] += rs2[tid + off]; }
        __syncthreads();
    }
    __shared__ float sh_mean, sh_inv;
    if (tid == 0) {
        float mean = rs[0] / (float)NEL;
        float var = rs2[0] / (float)NEL - mean * mean;
        sh_mean = mean;
        sh_inv = rsqrtf(var + EPSV);
    }
    __syncthreads();
    float mean = sh_mean, inv = sh_inv;
    for (int i = tid; i < NEL; i += 256) {
        int c = c0 + (i >> 12);
        int p = i & (HWN - 1);
        float v = x[((size_t)b * CC + c) * HWN + p];
        float t = (v - mean) * inv * gamma[c] + beta[c];
        size_t o = ((size_t)b * HWN + p) * CC + c;
        half_t h, l;
        split1(t, h, l);
        g_th[o] = h;
        g_tl[o] = l;
    }
}

// ---------------- per-row inverse sums of P (deterministic) ----------------
__global__ void rowsum_inv() {
    const size_t row = blockIdx.x;
    const __half2* p = (const __half2*)(g_ph + row * HWN);
    const int tid = threadIdx.x;
    float s = 0.f;
#pragma unroll
    for (int i = 0; i < 8; i++) {
        float2 v = __half22float2(p[tid + i * 256]);
        s += v.x + v.y;
    }
    __shared__ float red[256];
    red[tid] = s;
    __syncthreads();
    for (int off = 128; off > 0; off >>= 1) {
        if (tid < off) red[tid] += red[tid + off];
        __syncthreads();
    }
    if (tid == 0) g_rsi[row] = 1.f / red[0];
}

// ---------------- host launch ----------------
extern "C" void kernel_launch(void* const* d_in, const int* in_sizes, int n_in,
                              void* d_out, int out_size) {
    const float* x     = (const float*)d_in[0];
    const float* gamma = (const float*)d_in[1];
    const float* beta  = (const float*)d_in[2];
    const float* wq    = (const float*)d_in[3];
    const float* bq    = (const float*)d_in[4];
    const float* wk    = (const float*)d_in[5];
    const float* bk    = (const float*)d_in[6];
    const float* wv    = (const float*)d_in[7];
    const float* bv    = (const float*)d_in[8];
    const float* wp    = (const float*)d_in[9];
    const float* bp    = (const float*)d_in[10];
    float* out = (float*)d_out;

    half_t *pth, *ptl, *pwh, *pwph, *pqh, *pql, *pkh, *pvth, *pph, *paoh, *paol;
    float *pbqkv, *prsi;
    cudaGetSymbolAddress((void**)&pth,  g_th);
    cudaGetSymbolAddress((void**)&ptl,  g_tl);
    cudaGetSymbolAddress((void**)&pwh,  g_wh);
    cudaGetSymbolAddress((void**)&pwph, g_wph);
    cudaGetSymbolAddress((void**)&pbqkv, g_bqkv);
    cudaGetSymbolAddress((void**)&pqh,  g_qh);
    cudaGetSymbolAddress((void**)&pql,  g_ql);
    cudaGetSymbolAddress((void**)&pkh,  g_kh);
    cudaGetSymbolAddress((void**)&pvth, g_vth);
    cudaGetSymbolAddress((void**)&pph,  g_ph);
    cudaGetSymbolAddress((void**)&prsi, g_rsi);
    cudaGetSymbolAddress((void**)&paoh, g_aoh);
    cudaGetSymbolAddress((void**)&paol, g_aol);

    const int DSMEM = 3 * STG;  // 144KB
    cudaFuncSetAttribute(gemm_mma<4, true>,  cudaFuncAttributeMaxDynamicSharedMemorySize, DSMEM);
    cudaFuncSetAttribute(gemm_mma<5, true>,  cudaFuncAttributeMaxDynamicSharedMemorySize, DSMEM);
    cudaFuncSetAttribute(gemm_mma<6, false>, cudaFuncAttributeMaxDynamicSharedMemorySize, DSMEM);
    cudaFuncSetAttribute(gemm_mma<3, true>,  cudaFuncAttributeMaxDynamicSharedMemorySize, DSMEM);

    const float scale = 0.044194173824159216f;   // 512^-0.5
    const float alphaS = scale * 1.4426950408889634f;  // fold log2(e) for exp2
    const long SQC = (long)HWN * CC;
    const long SQQ = (long)HWN * HWN;

    // 1) convert weights/bias + groupnorm
    convert_w<<<dim3(CC * CC / 256, 4), 256>>>(wq, wk, wv, wp, bq, bk, bv);
    groupnorm_kernel<<<BB * NGROUP, 256>>>(x, gamma, beta);

    // 2) fused QKV: N = 1536 over stacked weights
    {
        dim3 grid(3 * CC / Bb_N, BB * HWN / Bb_M, 1);
        gemm_mma<4, true><<<grid, 256, DSMEM>>>(pth, ptl, pwh, pbqkv,
                                                nullptr, pqh, pql, pkh, pvth, nullptr,
                                                CC, CC, CC, CC, 0, 0, 0, 0.f);
    }

    // 3) P = exp2(Q K^T * scale * log2e)  (batched, fp16 out, fused exp)
    {
        dim3 grid(HWN / Bb_N, HWN / Bb_M, BB);
        gemm_mma<5, true><<<grid, 256, DSMEM>>>(pqh, pql, pkh,
                                                nullptr, nullptr, pph, nullptr, nullptr, nullptr, nullptr,
                                                CC, CC, CC, HWN, SQC, SQC, SQQ, alphaS);
    }

    // 4) per-row inverse sums
    rowsum_inv<<<BB * HWN, 256>>>();

    // 5) O = (P @ V) * inv_rowsum  (B = V^T, single-P mainloop)
    {
        dim3 grid(CC / Bb_N, HWN / Bb_M, BB);
        gemm_mma<6, false><<<grid, 256, DSMEM>>>(pph, nullptr, pvth,
                                                 nullptr, nullptr, paoh, paol, nullptr, nullptr, prsi,
                                                 HWN, HWN, HWN, CC, SQQ, (long)CC * HWN, SQC, 0.f);
    }

    // 6) proj + bias + residual, transposed store to (b,c,h,w)
    {
        dim3 grid(CC / Bb_N, BB * HWN / Bb_M, 1);
        gemm_mma<3, true><<<grid, 256, DSMEM>>>(paoh, paol, pwph,
                                                bp, out, nullptr, nullptr, nullptr, nullptr, x,
                                                CC, CC, CC, CC, 0, 0, 0, 0.f);
    }
}

// round 6
// speedup vs baseline: 5.8547x; 1.3270x over previous
#include <cuda_runtime.h>
#include <cuda_fp16.h>
#include <math.h>
#include <stdint.h>

#define BB 2
#define CC 512
#define HWN 4096
#define NGROUP 32
#define CPG 16
#define EPSV 1e-6f

typedef __half half_t;

// ---------------- scratch (static device globals; no allocs allowed) ----------------
__device__ half_t g_th [(size_t)BB * HWN * CC];   // groupnormed hi (b,n,c)
__device__ half_t g_tl [(size_t)BB * HWN * CC];   // groupnormed lo
__device__ half_t g_wh [(size_t)3 * CC * CC];     // [wq;wk;wv] fp16, rows = out-ch
__device__ half_t g_wph[(size_t)CC * CC];         // wp fp16
__device__ float  g_bqkv[3 * CC];                 // [bq;bk;bv]
__device__ half_t g_qh [(size_t)BB * HWN * CC];   // Q hi
__device__ half_t g_ql [(size_t)BB * HWN * CC];   // Q lo
__device__ half_t g_kh [(size_t)BB * HWN * CC];   // K single
__device__ half_t g_vth[(size_t)BB * CC * HWN];   // V^T single (b,c,n)
__device__ half_t g_ph [(size_t)BB * HWN * HWN];  // unnormalized probs fp16
__device__ float  g_rsi[(size_t)BB * HWN];        // 1 / rowsum
__device__ half_t g_aoh[(size_t)BB * HWN * CC];   // attn@V hi
__device__ half_t g_aol[(size_t)BB * HWN * CC];   // attn@V lo

// ================= helpers =================
__device__ __forceinline__ uint32_t smem_u32(const void* p) {
    uint32_t a;
    asm("{ .reg .u64 t; cvta.to.shared.u64 t, %1; cvt.u32.u64 %0, t; }" : "=r"(a) : "l"(p));
    return a;
}
#define CP16(dst, src) \
    asm volatile("cp.async.cg.shared.global [%0], [%1], 16;" :: "r"(dst), "l"(src))
#define CP_COMMIT() asm volatile("cp.async.commit_group;" ::: "memory")
#define CP_WAIT1()  asm volatile("cp.async.wait_group 1;" ::: "memory")

#define LDSM4(r, addr) \
    asm volatile("ldmatrix.sync.aligned.m8n8.x4.shared.b16 {%0,%1,%2,%3}, [%4];" \
        : "=r"((r)[0]), "=r"((r)[1]), "=r"((r)[2]), "=r"((r)[3]) : "r"(addr))

#define MMA_F16(d, a, b) \
    asm volatile("mma.sync.aligned.m16n8k16.row.col.f32.f16.f16.f32 " \
        "{%0,%1,%2,%3}, {%4,%5,%6,%7}, {%8,%9}, {%0,%1,%2,%3};" \
        : "+f"((d)[0]), "+f"((d)[1]), "+f"((d)[2]), "+f"((d)[3]) \
        : "r"((a)[0]), "r"((a)[1]), "r"((a)[2]), "r"((a)[3]), "r"((b)[0]), "r"((b)[1]))

__device__ __forceinline__ void split1(float v, half_t& h, half_t& l) {
    h = __float2half_rn(v);
    l = __float2half_rn(v - __half2float(h));
}

// ================= 2-term split-fp16 HMMA GEMM =================
// C[m,n] = sum_k A[m,k]*B[n,k] (TN); A = Ah(+Al if SPLIT_A), B single fp16.
// MODE 3: fp32 transposed out + bias + residual (final output)
// MODE 4: fused QKV routing: n<512 -> q split; <1024 -> k single; else v^T single
// MODE 5: P = exp2(acc * alpha) stored fp16 (batched; softmax numerator)
// MODE 6: out = acc * extra[row] (inv rowsum), split fp16 store (batched)
#define Bb_M 128
#define Bb_N 128
#define Bb_K 64
#define STG 49152  // bytes per smem stage (Ah, Al, B : 16KB each)

template <int MODE, bool SPLIT_A>
__global__ void __launch_bounds__(256, 1)
gemm_mma(const half_t* __restrict__ Ah, const half_t* __restrict__ Al,
         const half_t* __restrict__ B,
         const float* __restrict__ bias,
         float* __restrict__ Cf, half_t* __restrict__ Ch, half_t* __restrict__ Cl,
         half_t* __restrict__ C2, half_t* __restrict__ C3,
         const float* __restrict__ extra,
         int K, int lda, int ldb, int ldc,
         long sA, long sB, long sC, float alpha) {
    extern __shared__ __align__(1024) char smem[];
    const uint32_t sb32 = smem_u32(smem);
    const int tid = threadIdx.x;
    const int lane = tid & 31;
    const int wid = tid >> 5;
    const int wm = wid >> 2;
    const int wn = wid & 3;
    const long zz = blockIdx.z;

    Ah += zz * sA;
    if (SPLIT_A) Al += zz * sA;
    B += zz * sB;

    const int bm = blockIdx.y * Bb_M;
    const int bn = blockIdx.x * Bb_N;
    const int nck = K / Bb_K;

    auto issue = [&](int ck) {
        const int st = ck % 3;
        const int k0 = ck * Bb_K;
        const uint32_t sbase = sb32 + st * STG;
#pragma unroll
        for (int p = 0; p < 4; p++) {
            int idx = tid + p * 256;
            int r = idx >> 3;
            int c8 = idx & 7;
            uint32_t d = (uint32_t)(r * 128) + (uint32_t)((c8 * 16) ^ ((r & 7) << 4));
            CP16(sbase + d, Ah + (size_t)(bm + r) * lda + k0 + c8 * 8);
            if (SPLIT_A)
                CP16(sbase + 16384 + d, Al + (size_t)(bm + r) * lda + k0 + c8 * 8);
            CP16(sbase + 32768 + d, B + (size_t)(bn + r) * ldb + k0 + c8 * 8);
        }
        CP_COMMIT();
    };

    issue(0);
    issue(1);

    float acc[16][4];
#pragma unroll
    for (int i = 0; i < 16; i++)
#pragma unroll
        for (int j = 0; j < 4; j++) acc[i][j] = 0.f;

    const int arow = wm * 64 + (lane & 7) + (lane & 8);
    const uint32_t akx = ((lane >> 4) & 1) ? 16u : 0u;
    const int brow = wn * 32 + (lane & 7) + ((lane >> 4) & 1) * 8;
    const uint32_t bkx = (lane & 8) ? 16u : 0u;
    const uint32_t lxor = (uint32_t)((lane & 7) << 4);

    // double-buffered fragments
    uint32_t fah[2][4][4], fal[2][4][4], fbh[2][4][2];

    auto load_frags = [&](uint32_t ab, int kk, int buf) {
        const uint32_t kb = (uint32_t)(kk * 32);
#pragma unroll
        for (int mf = 0; mf < 4; mf++) {
            uint32_t ad = ab + (uint32_t)((arow + mf * 16) * 128) + ((kb + akx) ^ lxor);
            LDSM4(fah[buf][mf], ad);
            if (SPLIT_A) LDSM4(fal[buf][mf], ad + 16384);
        }
#pragma unroll
        for (int nfp = 0; nfp < 2; nfp++) {
            uint32_t bd = ab + 32768 + (uint32_t)((brow + nfp * 16) * 128) + ((kb + bkx) ^ lxor);
            uint32_t t[4];
            LDSM4(t, bd);
            fbh[buf][nfp * 2][0] = t[0]; fbh[buf][nfp * 2][1] = t[1];
            fbh[buf][nfp * 2 + 1][0] = t[2]; fbh[buf][nfp * 2 + 1][1] = t[3];
        }
    };

    for (int ck = 0; ck < nck; ck++) {
        CP_WAIT1();
        __syncthreads();
        if (ck + 2 < nck) issue(ck + 2);
        else CP_COMMIT();
        const uint32_t ab = sb32 + (uint32_t)((ck % 3) * STG);

        load_frags(ab, 0, 0);
#pragma unroll
        for (int kk = 0; kk < 4; kk++) {
            const int cur = kk & 1;
            if (kk < 3) load_frags(ab, kk + 1, cur ^ 1);
            // all hi-term MMAs first, then lo: same-acc reuse distance = 16
#pragma unroll
            for (int mf = 0; mf < 4; mf++)
#pragma unroll
                for (int nf = 0; nf < 4; nf++)
                    MMA_F16(acc[mf * 4 + nf], fah[cur][mf], fbh[cur][nf]);
            if (SPLIT_A) {
#pragma unroll
                for (int mf = 0; mf < 4; mf++)
#pragma unroll
                    for (int nf = 0; nf < 4; nf++)
                        MMA_F16(acc[mf * 4 + nf], fal[cur][mf], fbh[cur][nf]);
            }
        }
    }

    // ---------------- epilogue ----------------
    if (MODE == 5) Ch += zz * sC;
    if (MODE == 6) { Ch += zz * sC; Cl += zz * sC; }

#pragma unroll
    for (int mf = 0; mf < 4; mf++) {
#pragma unroll
        for (int nf = 0; nf < 4; nf++) {
            float* c = acc[mf * 4 + nf];
            const int m0 = bm + wm * 64 + mf * 16 + (lane >> 2);
            const int n0 = bn + wn * 32 + nf * 8 + 2 * (lane & 3);
#pragma unroll
            for (int hf = 0; hf < 2; hf++) {
                const int m = m0 + hf * 8;
                float v0 = c[hf * 2 + 0];
                float v1 = c[hf * 2 + 1];
                if (MODE == 5) {
                    __half2 xh = __floats2half2_rn(v0 * alpha, v1 * alpha);
                    *(__half2*)(Ch + (size_t)m * ldc + n0) = h2exp2(xh);
                } else if (MODE == 6) {
                    float inv = extra[zz * HWN + m];
                    v0 *= inv; v1 *= inv;
                    half_t h0, l0, h1, l1;
                    split1(v0, h0, l0);
                    split1(v1, h1, l1);
                    size_t o = (size_t)m * ldc + n0;
                    *(__half2*)(Ch + o) = __halves2half2(h0, h1);
                    *(__half2*)(Cl + o) = __halves2half2(l0, l1);
                } else if (MODE == 4) {
                    v0 += bias[n0]; v1 += bias[n0 + 1];
                    const int seg = n0 >> 9;
                    const int nn = n0 & 511;
                    if (seg == 0) {
                        half_t h0, l0, h1, l1;
                        split1(v0, h0, l0);
                        split1(v1, h1, l1);
                        size_t o = (size_t)m * CC + nn;
                        *(__half2*)(Ch + o) = __halves2half2(h0, h1);
                        *(__half2*)(Cl + o) = __halves2half2(l0, l1);
                    } else if (seg == 1) {
                        size_t o = (size_t)m * CC + nn;
                        *(__half2*)(C2 + o) = __floats2half2_rn(v0, v1);
                    } else {
                        const int bb = m >> 12;
                        const int tok = m & (HWN - 1);
                        size_t o = ((size_t)bb * CC + nn) * HWN + tok;
                        C3[o] = __float2half_rn(v0);
                        C3[o + HWN] = __float2half_rn(v1);
                    }
                } else {  // MODE 3: proj + bias + residual, transposed fp32
                    const int bb = m >> 12;
                    const int tok = m & (HWN - 1);
                    size_t o = ((size_t)bb * CC + n0) * HWN + tok;
                    Cf[o] = v0 + bias[n0] + extra[o];
                    Cf[o + HWN] = v1 + bias[n0 + 1] + extra[o + HWN];
                }
            }
        }
    }
}

// ---------------- weights fp32 -> fp16; bias concat ----------------
__global__ void convert_w(const float* __restrict__ w0, const float* __restrict__ w1,
                          const float* __restrict__ w2, const float* __restrict__ w3,
                          const float* __restrict__ b0, const float* __restrict__ b1,
                          const float* __restrict__ b2) {
    int i = blockIdx.x * 256 + threadIdx.x;
    int y = blockIdx.y;
    if (y < 3) {
        const float* w = (y == 0) ? w0 : (y == 1) ? w1 : w2;
        g_wh[(size_t)y * (CC * CC) + i] = __float2half_rn(w[i]);
        if (blockIdx.x < 2) {
            int j = blockIdx.x * 256 + threadIdx.x;
            const float* b = (y == 0) ? b0 : (y == 1) ? b1 : b2;
            g_bqkv[y * CC + j] = b[j];
        }
    } else {
        g_wph[i] = __float2half_rn(w3[i]);
    }
}

// ---------------- GroupNorm + transpose to (b,n,c), split fp16 ----------------
// One block per (batch, group). Pass 2: each thread handles one pixel's 16
// channels -> two 16B stores per output array (coalesced within thread).
__global__ void groupnorm_kernel(const float* __restrict__ x,
                                 const float* __restrict__ gamma,
                                 const float* __restrict__ beta) {
    const int b = blockIdx.x / NGROUP;
    const int g = blockIdx.x % NGROUP;
    const int c0 = g * CPG;
    const int tid = threadIdx.x;

    // pass 1: float4 sums over 16 channels x 4096 px
    const float4* xb = (const float4*)(x + ((size_t)b * CC + c0) * HWN);
    float s = 0.f, s2 = 0.f;
#pragma unroll 4
    for (int i = tid; i < CPG * HWN / 4; i += 256) {
        float4 v = xb[i];
        s += v.x + v.y + v.z + v.w;
        s2 += v.x * v.x + v.y * v.y + v.z * v.z + v.w * v.w;
    }
    __shared__ float rs[256], rs2[256];
    rs[tid] = s; rs2[tid] = s2;
    __syncthreads();
    for (int off = 128; off > 0; off >>= 1) {
        if (tid < off) { rs[tid] += rs[tid + off]; rs2[tid] += rs2[tid + off]; }
        __syncthreads();
    }
    __shared__ float sh_mean, sh_inv;
    __shared__ float sg[CPG], sbt[CPG];
    if (tid == 0) {
        float mean = rs[0] / (float)(CPG * HWN);
        float var = rs2[0] / (float)(CPG * HWN) - mean * mean;
        sh_mean = mean;
        sh_inv = rsqrtf(var + EPSV);
    }
    if (tid < CPG) { sg[tid] = gamma[c0 + tid]; sbt[tid] = beta[c0 + tid]; }
    __syncthreads();
    const float mean = sh_mean, inv = sh_inv;

    // pass 2
    const float* xc = x + ((size_t)b * CC + c0) * HWN;
    for (int p = tid; p < HWN; p += 256) {
        half_t hh[CPG], ll[CPG];
#pragma unroll
        for (int i = 0; i < CPG; i++) {
            float v = xc[(size_t)i * HWN + p];
            float t = (v - mean) * inv * sg[i] + sbt[i];
            split1(t, hh[i], ll[i]);
        }
        size_t o = ((size_t)b * HWN + p) * CC + c0;
        *(uint4*)(g_th + o) = *(uint4*)(hh);
        *(uint4*)(g_th + o + 8) = *(uint4*)(hh + 8);
        *(uint4*)(g_tl + o) = *(uint4*)(ll);
        *(uint4*)(g_tl + o + 8) = *(uint4*)(ll + 8);
    }
}

// ---------------- per-row inverse sums of P (deterministic) ----------------
__global__ void rowsum_inv() {
    const size_t row = blockIdx.x;
    const __half2* p = (const __half2*)(g_ph + row * HWN);
    const int tid = threadIdx.x;
    float s = 0.f;
#pragma unroll
    for (int i = 0; i < 8; i++) {
        float2 v = __half22float2(p[tid + i * 256]);
        s += v.x + v.y;
    }
    __shared__ float red[256];
    red[tid] = s;
    __syncthreads();
    for (int off = 128; off > 0; off >>= 1) {
        if (tid < off) red[tid] += red[tid + off];
        __syncthreads();
    }
    if (tid == 0) g_rsi[row] = 1.f / red[0];
}

// ---------------- host launch ----------------
extern "C" void kernel_launch(void* const* d_in, const int* in_sizes, int n_in,
                              void* d_out, int out_size) {
    const float* x     = (const float*)d_in[0];
    const float* gamma = (const float*)d_in[1];
    const float* beta  = (const float*)d_in[2];
    const float* wq    = (const float*)d_in[3];
    const float* bq    = (const float*)d_in[4];
    const float* wk    = (const float*)d_in[5];
    const float* bk    = (const float*)d_in[6];
    const float* wv    = (const float*)d_in[7];
    const float* bv    = (const float*)d_in[8];
    const float* wp    = (const float*)d_in[9];
    const float* bp    = (const float*)d_in[10];
    float* out = (float*)d_out;

    half_t *pth, *ptl, *pwh, *pwph, *pqh, *pql, *pkh, *pvth, *pph, *paoh, *paol;
    float *pbqkv, *prsi;
    cudaGetSymbolAddress((void**)&pth,  g_th);
    cudaGetSymbolAddress((void**)&ptl,  g_tl);
    cudaGetSymbolAddress((void**)&pwh,  g_wh);
    cudaGetSymbolAddress((void**)&pwph, g_wph);
    cudaGetSymbolAddress((void**)&pbqkv, g_bqkv);
    cudaGetSymbolAddress((void**)&pqh,  g_qh);
    cudaGetSymbolAddress((void**)&pql,  g_ql);
    cudaGetSymbolAddress((void**)&pkh,  g_kh);
    cudaGetSymbolAddress((void**)&pvth, g_vth);
    cudaGetSymbolAddress((void**)&pph,  g_ph);
    cudaGetSymbolAddress((void**)&prsi, g_rsi);
    cudaGetSymbolAddress((void**)&paoh, g_aoh);
    cudaGetSymbolAddress((void**)&paol, g_aol);

    const int DSMEM = 3 * STG;  // 144KB
    cudaFuncSetAttribute(gemm_mma<4, true>,  cudaFuncAttributeMaxDynamicSharedMemorySize, DSMEM);
    cudaFuncSetAttribute(gemm_mma<5, true>,  cudaFuncAttributeMaxDynamicSharedMemorySize, DSMEM);
    cudaFuncSetAttribute(gemm_mma<6, false>, cudaFuncAttributeMaxDynamicSharedMemorySize, DSMEM);
    cudaFuncSetAttribute(gemm_mma<3, true>,  cudaFuncAttributeMaxDynamicSharedMemorySize, DSMEM);

    const float scale = 0.044194173824159216f;         // 512^-0.5
    const float alphaS = scale * 1.4426950408889634f;  // fold log2(e) for exp2
    const long SQC = (long)HWN * CC;
    const long SQQ = (long)HWN * HWN;

    // 1) convert weights/bias + groupnorm
    convert_w<<<dim3(CC * CC / 256, 4), 256>>>(wq, wk, wv, wp, bq, bk, bv);
    groupnorm_kernel<<<BB * NGROUP, 256>>>(x, gamma, beta);

    // 2) fused QKV: N = 1536 over stacked weights
    {
        dim3 grid(3 * CC / Bb_N, BB * HWN / Bb_M, 1);
        gemm_mma<4, true><<<grid, 256, DSMEM>>>(pth, ptl, pwh, pbqkv,
                                                nullptr, pqh, pql, pkh, pvth, nullptr,
                                                CC, CC, CC, CC, 0, 0, 0, 0.f);
    }

    // 3) P = exp2(Q K^T * scale * log2e)  (batched, fp16 out, fused exp)
    {
        dim3 grid(HWN / Bb_N, HWN / Bb_M, BB);
        gemm_mma<5, true><<<grid, 256, DSMEM>>>(pqh, pql, pkh,
                                                nullptr, nullptr, pph, nullptr, nullptr, nullptr, nullptr,
                                                CC, CC, CC, HWN, SQC, SQC, SQQ, alphaS);
    }

    // 4) per-row inverse sums
    rowsum_inv<<<BB * HWN, 256>>>();

    // 5) O = (P @ V) * inv_rowsum  (B = V^T, single-P mainloop)
    {
        dim3 grid(CC / Bb_N, HWN / Bb_M, BB);
        gemm_mma<6, false><<<grid, 256, DSMEM>>>(pph, nullptr, pvth,
                                                 nullptr, nullptr, paoh, paol, nullptr, nullptr, prsi,
                                                 HWN, HWN, HWN, CC, SQQ, (long)CC * HWN, SQC, 0.f);
    }

    // 6) proj + bias + residual, transposed store to (b,c,h,w)
    {
        dim3 grid(CC / Bb_N, BB * HWN / Bb_M, 1);
        gemm_mma<3, true><<<grid, 256, DSMEM>>>(paoh, paol, pwph,
                                                bp, out, nullptr, nullptr, nullptr, nullptr, x,
                                                CC, CC, CC, CC, 0, 0, 0, 0.f);
    }
}

// round 7
// speedup vs baseline: 7.8203x; 1.3357x over previous
#include <cuda_runtime.h>
#include <cuda_fp16.h>
#include <math.h>
#include <stdint.h>

#define BB 2
#define CC 512
#define HWN 4096
#define NGROUP 32
#define CPG 16
#define EPSV 1e-6f

typedef __half half_t;

// ---------------- scratch (static device globals; no allocs allowed) ----------------
__device__ half_t g_t  [(size_t)BB * HWN * CC];   // groupnormed (b,n,c) fp16
__device__ half_t g_wh [(size_t)3 * CC * CC];     // [wq;wk;wv] fp16, rows = out-ch
__device__ half_t g_wph[(size_t)CC * CC];         // wp fp16
__device__ float  g_bqkv[3 * CC];                 // [bq;bk;bv]
__device__ half_t g_q  [(size_t)BB * HWN * CC];   // Q fp16
__device__ half_t g_k  [(size_t)BB * HWN * CC];   // K fp16
__device__ half_t g_vt [(size_t)BB * CC * HWN];   // V^T fp16 (b,c,n)
__device__ half_t g_p  [(size_t)BB * HWN * HWN];  // unnormalized probs fp16
__device__ float  g_rsi[(size_t)BB * HWN];        // 1 / rowsum
__device__ half_t g_ao [(size_t)BB * HWN * CC];   // attn@V fp16

// ================= helpers =================
__device__ __forceinline__ uint32_t smem_u32(const void* p) {
    uint32_t a;
    asm("{ .reg .u64 t; cvta.to.shared.u64 t, %1; cvt.u32.u64 %0, t; }" : "=r"(a) : "l"(p));
    return a;
}
#define CP16(dst, src) \
    asm volatile("cp.async.cg.shared.global [%0], [%1], 16;" :: "r"(dst), "l"(src))
#define CP_COMMIT() asm volatile("cp.async.commit_group;" ::: "memory")
#define CP_WAIT1()  asm volatile("cp.async.wait_group 1;" ::: "memory")

#define LDSM4(r, addr) \
    asm volatile("ldmatrix.sync.aligned.m8n8.x4.shared.b16 {%0,%1,%2,%3}, [%4];" \
        : "=r"((r)[0]), "=r"((r)[1]), "=r"((r)[2]), "=r"((r)[3]) : "r"(addr))

#define MMA_F16(d, a, b) \
    asm volatile("mma.sync.aligned.m16n8k16.row.col.f32.f16.f16.f32 " \
        "{%0,%1,%2,%3}, {%4,%5,%6,%7}, {%8,%9}, {%0,%1,%2,%3};" \
        : "+f"((d)[0]), "+f"((d)[1]), "+f"((d)[2]), "+f"((d)[3]) \
        : "r"((a)[0]), "r"((a)[1]), "r"((a)[2]), "r"((a)[3]), "r"((b)[0]), "r"((b)[1]))

// ================= single-fp16 HMMA GEMM (fp32 accum) =================
// C[m,n] = sum_k A[m,k]*B[n,k] (TN), A and B fp16 row-major [*,K].
// MODE 3: fp32 transposed out + bias + residual (final output)
// MODE 4: fused QKV routing: n<512 -> q; <1024 -> k; else v^T (transposed)
// MODE 5: P = exp2(acc * alpha) stored fp16 (batched; softmax numerator)
// MODE 6: out = acc * extra[row] (inv rowsum), fp16 store (batched)
#define Bb_M 128
#define Bb_N 128
#define Bb_K 64
#define STG 32768  // bytes per smem stage (A, B : 16KB each)

template <int MODE>
__global__ void __launch_bounds__(256, 1)
gemm_mma(const half_t* __restrict__ A, const half_t* __restrict__ B,
         const float* __restrict__ bias,
         float* __restrict__ Cf, half_t* __restrict__ Ch,
         half_t* __restrict__ C2, half_t* __restrict__ C3,
         const float* __restrict__ extra,
         int K, int lda, int ldb, int ldc,
         long sA, long sB, long sC, float alpha) {
    extern __shared__ __align__(1024) char smem[];
    const uint32_t sb32 = smem_u32(smem);
    const int tid = threadIdx.x;
    const int lane = tid & 31;
    const int wid = tid >> 5;
    const int wm = wid >> 2;
    const int wn = wid & 3;
    const long zz = blockIdx.z;

    A += zz * sA;
    B += zz * sB;

    const int bm = blockIdx.y * Bb_M;
    const int bn = blockIdx.x * Bb_N;
    const int nck = K / Bb_K;

    auto issue = [&](int ck) {
        const int st = ck % 3;
        const int k0 = ck * Bb_K;
        const uint32_t sbase = sb32 + st * STG;
#pragma unroll
        for (int p = 0; p < 4; p++) {
            int idx = tid + p * 256;
            int r = idx >> 3;
            int c8 = idx & 7;
            uint32_t d = (uint32_t)(r * 128) + (uint32_t)((c8 * 16) ^ ((r & 7) << 4));
            CP16(sbase + d,         A + (size_t)(bm + r) * lda + k0 + c8 * 8);
            CP16(sbase + 16384 + d, B + (size_t)(bn + r) * ldb + k0 + c8 * 8);
        }
        CP_COMMIT();
    };

    issue(0);
    issue(1);

    float acc[16][4];
#pragma unroll
    for (int i = 0; i < 16; i++)
#pragma unroll
        for (int j = 0; j < 4; j++) acc[i][j] = 0.f;

    const int arow = wm * 64 + (lane & 7) + (lane & 8);
    const uint32_t akx = ((lane >> 4) & 1) ? 16u : 0u;
    const int brow = wn * 32 + (lane & 7) + ((lane >> 4) & 1) * 8;
    const uint32_t bkx = (lane & 8) ? 16u : 0u;
    const uint32_t lxor = (uint32_t)((lane & 7) << 4);

    // double-buffered fragments
    uint32_t fa[2][4][4], fb[2][4][2];

    auto load_frags = [&](uint32_t ab, int kk, int buf) {
        const uint32_t kb = (uint32_t)(kk * 32);
#pragma unroll
        for (int mf = 0; mf < 4; mf++) {
            uint32_t ad = ab + (uint32_t)((arow + mf * 16) * 128) + ((kb + akx) ^ lxor);
            LDSM4(fa[buf][mf], ad);
        }
#pragma unroll
        for (int nfp = 0; nfp < 2; nfp++) {
            uint32_t bd = ab + 16384 + (uint32_t)((brow + nfp * 16) * 128) + ((kb + bkx) ^ lxor);
            uint32_t t[4];
            LDSM4(t, bd);
            fb[buf][nfp * 2][0] = t[0]; fb[buf][nfp * 2][1] = t[1];
            fb[buf][nfp * 2 + 1][0] = t[2]; fb[buf][nfp * 2 + 1][1] = t[3];
        }
    };

    for (int ck = 0; ck < nck; ck++) {
        CP_WAIT1();
        __syncthreads();
        if (ck + 2 < nck) issue(ck + 2);
        else CP_COMMIT();
        const uint32_t ab = sb32 + (uint32_t)((ck % 3) * STG);

        load_frags(ab, 0, 0);
#pragma unroll
        for (int kk = 0; kk < 4; kk++) {
            const int cur = kk & 1;
            if (kk < 3) load_frags(ab, kk + 1, cur ^ 1);
#pragma unroll
            for (int mf = 0; mf < 4; mf++)
#pragma unroll
                for (int nf = 0; nf < 4; nf++)
                    MMA_F16(acc[mf * 4 + nf], fa[cur][mf], fb[cur][nf]);
        }
    }

    // ---------------- epilogue ----------------
    if (MODE == 5 || MODE == 6) Ch += zz * sC;

#pragma unroll
    for (int mf = 0; mf < 4; mf++) {
#pragma unroll
        for (int nf = 0; nf < 4; nf++) {
            float* c = acc[mf * 4 + nf];
            const int m0 = bm + wm * 64 + mf * 16 + (lane >> 2);
            const int n0 = bn + wn * 32 + nf * 8 + 2 * (lane & 3);
#pragma unroll
            for (int hf = 0; hf < 2; hf++) {
                const int m = m0 + hf * 8;
                float v0 = c[hf * 2 + 0];
                float v1 = c[hf * 2 + 1];
                if (MODE == 5) {
                    __half2 xh = __floats2half2_rn(v0 * alpha, v1 * alpha);
                    *(__half2*)(Ch + (size_t)m * ldc + n0) = h2exp2(xh);
                } else if (MODE == 6) {
                    float inv = extra[zz * HWN + m];
                    *(__half2*)(Ch + (size_t)m * ldc + n0) =
                        __floats2half2_rn(v0 * inv, v1 * inv);
                } else if (MODE == 4) {
                    v0 += bias[n0]; v1 += bias[n0 + 1];
                    const int seg = n0 >> 9;
                    const int nn = n0 & 511;
                    if (seg == 0) {
                        *(__half2*)(Ch + (size_t)m * CC + nn) = __floats2half2_rn(v0, v1);
                    } else if (seg == 1) {
                        *(__half2*)(C2 + (size_t)m * CC + nn) = __floats2half2_rn(v0, v1);
                    } else {
                        const int bb = m >> 12;
                        const int tok = m & (HWN - 1);
                        size_t o = ((size_t)bb * CC + nn) * HWN + tok;
                        C3[o] = __float2half_rn(v0);
                        C3[o + HWN] = __float2half_rn(v1);
                    }
                } else {  // MODE 3: proj + bias + residual, transposed fp32
                    const int bb = m >> 12;
                    const int tok = m & (HWN - 1);
                    size_t o = ((size_t)bb * CC + n0) * HWN + tok;
                    Cf[o] = v0 + bias[n0] + extra[o];
                    Cf[o + HWN] = v1 + bias[n0 + 1] + extra[o + HWN];
                }
            }
        }
    }
}

// ---------------- weights fp32 -> fp16; bias concat ----------------
__global__ void convert_w(const float* __restrict__ w0, const float* __restrict__ w1,
                          const float* __restrict__ w2, const float* __restrict__ w3,
                          const float* __restrict__ b0, const float* __restrict__ b1,
                          const float* __restrict__ b2) {
    int i = blockIdx.x * 256 + threadIdx.x;
    int y = blockIdx.y;
    if (y < 3) {
        const float* w = (y == 0) ? w0 : (y == 1) ? w1 : w2;
        g_wh[(size_t)y * (CC * CC) + i] = __float2half_rn(w[i]);
        if (blockIdx.x < 2) {
            int j = blockIdx.x * 256 + threadIdx.x;
            const float* b = (y == 0) ? b0 : (y == 1) ? b1 : b2;
            g_bqkv[y * CC + j] = b[j];
        }
    } else {
        g_wph[i] = __float2half_rn(w3[i]);
    }
}

// ---------------- GroupNorm + transpose to (b,n,c), fp16 ----------------
__global__ void groupnorm_kernel(const float* __restrict__ x,
                                 const float* __restrict__ gamma,
                                 const float* __restrict__ beta) {
    const int b = blockIdx.x / NGROUP;
    const int g = blockIdx.x % NGROUP;
    const int c0 = g * CPG;
    const int tid = threadIdx.x;

    const float4* xb = (const float4*)(x + ((size_t)b * CC + c0) * HWN);
    float s = 0.f, s2 = 0.f;
#pragma unroll 4
    for (int i = tid; i < CPG * HWN / 4; i += 256) {
        float4 v = xb[i];
        s += v.x + v.y + v.z + v.w;
        s2 += v.x * v.x + v.y * v.y + v.z * v.z + v.w * v.w;
    }
    __shared__ float rs[256], rs2[256];
    rs[tid] = s; rs2[tid] = s2;
    __syncthreads();
    for (int off = 128; off > 0; off >>= 1) {
        if (tid < off) { rs[tid] += rs[tid + off]; rs2[tid] += rs2[tid + off]; }
        __syncthreads();
    }
    __shared__ float sh_mean, sh_inv;
    __shared__ float sg[CPG], sbt[CPG];
    if (tid == 0) {
        float mean = rs[0] / (float)(CPG * HWN);
        float var = rs2[0] / (float)(CPG * HWN) - mean * mean;
        sh_mean = mean;
        sh_inv = rsqrtf(var + EPSV);
    }
    if (tid < CPG) { sg[tid] = gamma[c0 + tid]; sbt[tid] = beta[c0 + tid]; }
    __syncthreads();
    const float mean = sh_mean, inv = sh_inv;

    const float* xc = x + ((size_t)b * CC + c0) * HWN;
    for (int p = tid; p < HWN; p += 256) {
        half_t hh[CPG];
#pragma unroll
        for (int i = 0; i < CPG; i++) {
            float v = xc[(size_t)i * HWN + p];
            hh[i] = __float2half_rn((v - mean) * inv * sg[i] + sbt[i]);
        }
        size_t o = ((size_t)b * HWN + p) * CC + c0;
        *(uint4*)(g_t + o) = *(uint4*)(hh);
        *(uint4*)(g_t + o + 8) = *(uint4*)(hh + 8);
    }
}

// ---------------- per-row inverse sums of P (deterministic) ----------------
__global__ void rowsum_inv() {
    const size_t row = blockIdx.x;
    const __half2* p = (const __half2*)(g_p + row * HWN);
    const int tid = threadIdx.x;
    float s = 0.f;
#pragma unroll
    for (int i = 0; i < 8; i++) {
        float2 v = __half22float2(p[tid + i * 256]);
        s += v.x + v.y;
    }
    __shared__ float red[256];
    red[tid] = s;
    __syncthreads();
    for (int off = 128; off > 0; off >>= 1) {
        if (tid < off) red[tid] += red[tid + off];
        __syncthreads();
    }
    if (tid == 0) g_rsi[row] = 1.f / red[0];
}

// ---------------- host launch ----------------
extern "C" void kernel_launch(void* const* d_in, const int* in_sizes, int n_in,
                              void* d_out, int out_size) {
    const float* x     = (const float*)d_in[0];
    const float* gamma = (const float*)d_in[1];
    const float* beta  = (const float*)d_in[2];
    const float* wq    = (const float*)d_in[3];
    const float* bq    = (const float*)d_in[4];
    const float* wk    = (const float*)d_in[5];
    const float* bk    = (const float*)d_in[6];
    const float* wv    = (const float*)d_in[7];
    const float* bv    = (const float*)d_in[8];
    const float* wp    = (const float*)d_in[9];
    const float* bp    = (const float*)d_in[10];
    float* out = (float*)d_out;

    half_t *pt, *pwh, *pwph, *pq, *pk, *pvt, *pp, *pao;
    float *pbqkv, *prsi;
    cudaGetSymbolAddress((void**)&pt,   g_t);
    cudaGetSymbolAddress((void**)&pwh,  g_wh);
    cudaGetSymbolAddress((void**)&pwph, g_wph);
    cudaGetSymbolAddress((void**)&pbqkv, g_bqkv);
    cudaGetSymbolAddress((void**)&pq,   g_q);
    cudaGetSymbolAddress((void**)&pk,   g_k);
    cudaGetSymbolAddress((void**)&pvt,  g_vt);
    cudaGetSymbolAddress((void**)&pp,   g_p);
    cudaGetSymbolAddress((void**)&prsi, g_rsi);
    cudaGetSymbolAddress((void**)&pao,  g_ao);

    const int DSMEM = 3 * STG;  // 96KB
    cudaFuncSetAttribute(gemm_mma<4>, cudaFuncAttributeMaxDynamicSharedMemorySize, DSMEM);
    cudaFuncSetAttribute(gemm_mma<5>, cudaFuncAttributeMaxDynamicSharedMemorySize, DSMEM);
    cudaFuncSetAttribute(gemm_mma<6>, cudaFuncAttributeMaxDynamicSharedMemorySize, DSMEM);
    cudaFuncSetAttribute(gemm_mma<3>, cudaFuncAttributeMaxDynamicSharedMemorySize, DSMEM);

    const float scale = 0.044194173824159216f;         // 512^-0.5
    const float alphaS = scale * 1.4426950408889634f;  // fold log2(e) for exp2
    const long SQC = (long)HWN * CC;
    const long SQQ = (long)HWN * HWN;

    // 1) convert weights/bias + groupnorm
    convert_w<<<dim3(CC * CC / 256, 4), 256>>>(wq, wk, wv, wp, bq, bk, bv);
    groupnorm_kernel<<<BB * NGROUP, 256>>>(x, gamma, beta);

    // 2) fused QKV: N = 1536 over stacked weights
    {
        dim3 grid(3 * CC / Bb_N, BB * HWN / Bb_M, 1);
        gemm_mma<4><<<grid, 256, DSMEM>>>(pt, pwh, pbqkv,
                                          nullptr, pq, pk, pvt, nullptr,
                                          CC, CC, CC, CC, 0, 0, 0, 0.f);
    }

    // 3) P = exp2(Q K^T * scale * log2e)  (batched, fp16 out, fused exp)
    {
        dim3 grid(HWN / Bb_N, HWN / Bb_M, BB);
        gemm_mma<5><<<grid, 256, DSMEM>>>(pq, pk, nullptr,
                                          nullptr, pp, nullptr, nullptr, nullptr,
                                          CC, CC, CC, HWN, SQC, SQC, SQQ, alphaS);
    }

    // 4) per-row inverse sums
    rowsum_inv<<<BB * HWN, 256>>>();

    // 5) O = (P @ V) * inv_rowsum  (B = V^T)
    {
        dim3 grid(CC / Bb_N, HWN / Bb_M, BB);
        gemm_mma<6><<<grid, 256, DSMEM>>>(pp, pvt, nullptr,
                                          nullptr, pao, nullptr, nullptr, prsi,
                                          HWN, HWN, HWN, CC, SQQ, (long)CC * HWN, SQC, 0.f);
    }

    // 6) proj + bias + residual, transposed store to (b,c,h,w)
    {
        dim3 grid(CC / Bb_N, BB * HWN / Bb_M, 1);
        gemm_mma<3><<<grid, 256, DSMEM>>>(pao, pwph, bp,
                                          out, nullptr, nullptr, nullptr, x,
                                          CC, CC, CC, CC, 0, 0, 0, 0.f);
    }
}

// round 8
// speedup vs baseline: 9.2677x; 1.1851x over previous
#include <cuda_runtime.h>
#include <cuda_fp16.h>
#include <math.h>
#include <stdint.h>

#define BB 2
#define CC 512
#define HWN 4096
#define NGROUP 32
#define CPG 16
#define EPSV 1e-6f
#define NSLICE 8
#define SLPX (HWN / NSLICE)  // 512 px per slice

typedef __half half_t;

// ---------------- scratch (static device globals; no allocs allowed) ----------------
__device__ half_t g_t  [(size_t)BB * HWN * CC];   // groupnormed (b,n,c) fp16
__device__ half_t g_wh [(size_t)3 * CC * CC];     // [wq;wk;wv] fp16, rows = out-ch
__device__ half_t g_wph[(size_t)CC * CC];         // wp fp16
__device__ float  g_bqkv[3 * CC];                 // [bq;bk;bv]
__device__ half_t g_q  [(size_t)BB * HWN * CC];   // Q fp16
__device__ half_t g_k  [(size_t)BB * HWN * CC];   // K fp16
__device__ half_t g_vt [(size_t)BB * CC * HWN];   // V^T fp16 (b,c,n)
__device__ half_t g_p  [(size_t)BB * HWN * HWN];  // unnormalized probs fp16
__device__ float  g_rsi[(size_t)BB * HWN];        // 1 / rowsum
__device__ half_t g_ao [(size_t)BB * HWN * CC];   // attn@V fp16
__device__ float  g_gnp[BB * NGROUP * NSLICE * 2]; // groupnorm partial sums
__device__ float  g_gnm[BB * NGROUP * 2];          // mean, inv per group

// ================= helpers =================
__device__ __forceinline__ uint32_t smem_u32(const void* p) {
    uint32_t a;
    asm("{ .reg .u64 t; cvta.to.shared.u64 t, %1; cvt.u32.u64 %0, t; }" : "=r"(a) : "l"(p));
    return a;
}
#define CP16(dst, src) \
    asm volatile("cp.async.cg.shared.global [%0], [%1], 16;" :: "r"(dst), "l"(src))
#define CP_COMMIT() asm volatile("cp.async.commit_group;" ::: "memory")
#define CP_WAIT1()  asm volatile("cp.async.wait_group 1;" ::: "memory")

#define LDSM4(r, addr) \
    asm volatile("ldmatrix.sync.aligned.m8n8.x4.shared.b16 {%0,%1,%2,%3}, [%4];" \
        : "=r"((r)[0]), "=r"((r)[1]), "=r"((r)[2]), "=r"((r)[3]) : "r"(addr))

#define MMA_F16(d, a, b) \
    asm volatile("mma.sync.aligned.m16n8k16.row.col.f32.f16.f16.f32 " \
        "{%0,%1,%2,%3}, {%4,%5,%6,%7}, {%8,%9}, {%0,%1,%2,%3};" \
        : "+f"((d)[0]), "+f"((d)[1]), "+f"((d)[2]), "+f"((d)[3]) \
        : "r"((a)[0]), "r"((a)[1]), "r"((a)[2]), "r"((a)[3]), "r"((b)[0]), "r"((b)[1]))

// ================= single-fp16 HMMA GEMM (fp32 accum), 2 CTAs/SM =================
// C[m,n] = sum_k A[m,k]*B[n,k] (TN), A and B fp16 row-major [*,K].
// MODE 3: fp32 transposed out + bias + residual (final output)
// MODE 4: fused QKV routing: n<512 -> q; <1024 -> k; else v^T (transposed)
// MODE 5: P = exp2(acc * alpha) stored fp16 (batched; softmax numerator)
// MODE 6: out = acc * extra[row] (inv rowsum), fp16 store (batched)
#define Bb_M 128
#define Bb_N 128
#define Bb_K 64
#define STG 32768  // bytes per smem stage (A, B : 16KB each)

template <int MODE>
__global__ void __launch_bounds__(256, 2)
gemm_mma(const half_t* __restrict__ A, const half_t* __restrict__ B,
         const float* __restrict__ bias,
         float* __restrict__ Cf, half_t* __restrict__ Ch,
         half_t* __restrict__ C2, half_t* __restrict__ C3,
         const float* __restrict__ extra,
         int K, int lda, int ldb, int ldc,
         long sA, long sB, long sC, float alpha) {
    extern __shared__ __align__(1024) char smem[];
    const uint32_t sb32 = smem_u32(smem);
    const int tid = threadIdx.x;
    const int lane = tid & 31;
    const int wid = tid >> 5;
    const int wm = wid >> 2;
    const int wn = wid & 3;
    const long zz = blockIdx.z;

    A += zz * sA;
    B += zz * sB;

    const int bm = blockIdx.y * Bb_M;
    const int bn = blockIdx.x * Bb_N;
    const int nck = K / Bb_K;

    auto issue = [&](int ck) {
        const int st = ck % 3;
        const int k0 = ck * Bb_K;
        const uint32_t sbase = sb32 + st * STG;
#pragma unroll
        for (int p = 0; p < 4; p++) {
            int idx = tid + p * 256;
            int r = idx >> 3;
            int c8 = idx & 7;
            uint32_t d = (uint32_t)(r * 128) + (uint32_t)((c8 * 16) ^ ((r & 7) << 4));
            CP16(sbase + d,         A + (size_t)(bm + r) * lda + k0 + c8 * 8);
            CP16(sbase + 16384 + d, B + (size_t)(bn + r) * ldb + k0 + c8 * 8);
        }
        CP_COMMIT();
    };

    issue(0);
    issue(1);

    float acc[16][4];
#pragma unroll
    for (int i = 0; i < 16; i++)
#pragma unroll
        for (int j = 0; j < 4; j++) acc[i][j] = 0.f;

    const int arow = wm * 64 + (lane & 7) + (lane & 8);
    const uint32_t akx = ((lane >> 4) & 1) ? 16u : 0u;
    const int brow = wn * 32 + (lane & 7) + ((lane >> 4) & 1) * 8;
    const uint32_t bkx = (lane & 8) ? 16u : 0u;
    const uint32_t lxor = (uint32_t)((lane & 7) << 4);

    for (int ck = 0; ck < nck; ck++) {
        CP_WAIT1();
        __syncthreads();
        if (ck + 2 < nck) issue(ck + 2);
        else CP_COMMIT();
        const uint32_t ab = sb32 + (uint32_t)((ck % 3) * STG);

#pragma unroll
        for (int kk = 0; kk < 4; kk++) {
            const uint32_t kb = (uint32_t)(kk * 32);
            uint32_t fa[4][4], fb[4][2];
#pragma unroll
            for (int mf = 0; mf < 4; mf++) {
                uint32_t ad = ab + (uint32_t)((arow + mf * 16) * 128) + ((kb + akx) ^ lxor);
                LDSM4(fa[mf], ad);
            }
#pragma unroll
            for (int nfp = 0; nfp < 2; nfp++) {
                uint32_t bd = ab + 16384 + (uint32_t)((brow + nfp * 16) * 128) + ((kb + bkx) ^ lxor);
                uint32_t t[4];
                LDSM4(t, bd);
                fb[nfp * 2][0] = t[0]; fb[nfp * 2][1] = t[1];
                fb[nfp * 2 + 1][0] = t[2]; fb[nfp * 2 + 1][1] = t[3];
            }
#pragma unroll
            for (int mf = 0; mf < 4; mf++)
#pragma unroll
                for (int nf = 0; nf < 4; nf++)
                    MMA_F16(acc[mf * 4 + nf], fa[mf], fb[nf]);
        }
    }

    // ---------------- epilogue ----------------
    if (MODE == 5 || MODE == 6) Ch += zz * sC;

#pragma unroll
    for (int mf = 0; mf < 4; mf++) {
#pragma unroll
        for (int nf = 0; nf < 4; nf++) {
            float* c = acc[mf * 4 + nf];
            const int m0 = bm + wm * 64 + mf * 16 + (lane >> 2);
            const int n0 = bn + wn * 32 + nf * 8 + 2 * (lane & 3);
#pragma unroll
            for (int hf = 0; hf < 2; hf++) {
                const int m = m0 + hf * 8;
                float v0 = c[hf * 2 + 0];
                float v1 = c[hf * 2 + 1];
                if (MODE == 5) {
                    __half2 xh = __floats2half2_rn(v0 * alpha, v1 * alpha);
                    *(__half2*)(Ch + (size_t)m * ldc + n0) = h2exp2(xh);
                } else if (MODE == 6) {
                    float inv = extra[zz * HWN + m];
                    *(__half2*)(Ch + (size_t)m * ldc + n0) =
                        __floats2half2_rn(v0 * inv, v1 * inv);
                } else if (MODE == 4) {
                    v0 += bias[n0]; v1 += bias[n0 + 1];
                    const int seg = n0 >> 9;
                    const int nn = n0 & 511;
                    if (seg == 0) {
                        *(__half2*)(Ch + (size_t)m * CC + nn) = __floats2half2_rn(v0, v1);
                    } else if (seg == 1) {
                        *(__half2*)(C2 + (size_t)m * CC + nn) = __floats2half2_rn(v0, v1);
                    } else {
                        const int bb = m >> 12;
                        const int tok = m & (HWN - 1);
                        size_t o = ((size_t)bb * CC + nn) * HWN + tok;
                        C3[o] = __float2half_rn(v0);
                        C3[o + HWN] = __float2half_rn(v1);
                    }
                } else {  // MODE 3: proj + bias + residual, transposed fp32
                    const int bb = m >> 12;
                    const int tok = m & (HWN - 1);
                    size_t o = ((size_t)bb * CC + n0) * HWN + tok;
                    Cf[o] = v0 + bias[n0] + extra[o];
                    Cf[o + HWN] = v1 + bias[n0 + 1] + extra[o + HWN];
                }
            }
        }
    }
}

// ---------------- weights fp32 -> fp16; bias concat ----------------
__global__ void convert_w(const float* __restrict__ w0, const float* __restrict__ w1,
                          const float* __restrict__ w2, const float* __restrict__ w3,
                          const float* __restrict__ b0, const float* __restrict__ b1,
                          const float* __restrict__ b2) {
    int i = blockIdx.x * 256 + threadIdx.x;
    int y = blockIdx.y;
    if (y < 3) {
        const float* w = (y == 0) ? w0 : (y == 1) ? w1 : w2;
        g_wh[(size_t)y * (CC * CC) + i] = __float2half_rn(w[i]);
        if (blockIdx.x < 2) {
            int j = blockIdx.x * 256 + threadIdx.x;
            const float* b = (y == 0) ? b0 : (y == 1) ? b1 : b2;
            g_bqkv[y * CC + j] = b[j];
        }
    } else {
        g_wph[i] = __float2half_rn(w3[i]);
    }
}

// ---------------- GroupNorm, 3-phase for full-chip occupancy ----------------
// Phase 1: partial sums per (b, group, slice). grid (NSLICE, NGROUP, BB).
__global__ void gn_partial(const float* __restrict__ x) {
    const int s = blockIdx.x, g = blockIdx.y, b = blockIdx.z;
    const int tid = threadIdx.x;
    const float* xc = x + ((size_t)b * CC + g * CPG) * HWN + s * SLPX;
    float sum = 0.f, sum2 = 0.f;
#pragma unroll
    for (int i = 0; i < CPG; i++) {
        // 512 px = 128 float4; 256 threads -> half the threads idle per row? No:
        // use 2 float4 per thread over 16 rows: tid covers 128 -> tid&127, two rows per pass
        int row = i;
        const float4* xr = (const float4*)(xc + (size_t)row * HWN);
        if (tid < 128) {
            float4 v = xr[tid];
            sum += v.x + v.y + v.z + v.w;
            sum2 += v.x * v.x + v.y * v.y + v.z * v.z + v.w * v.w;
        } else {
            // second half of threads: (no-op, folded below)
        }
    }
    // use all 256 threads: redo with proper mapping (tid -> (row pair))
    // NOTE: above loop only used tid<128; add the other half:
    if (tid >= 128) {
        int t = tid - 128;
#pragma unroll
        for (int i = 0; i < CPG; i++) {
            // nothing extra; kept simple
            (void)t; (void)i;
        }
    }
    __shared__ float rs[256], rs2[256];
    rs[tid] = sum; rs2[tid] = sum2;
    __syncthreads();
    for (int off = 128; off > 0; off >>= 1) {
        if (tid < off) { rs[tid] += rs[tid + off]; rs2[tid] += rs2[tid + off]; }
        __syncthreads();
    }
    if (tid == 0) {
        int o = ((b * NGROUP + g) * NSLICE + s) * 2;
        g_gnp[o] = rs[0];
        g_gnp[o + 1] = rs2[0];
    }
}

// Phase 2: finalize mean/inv per (b, group). 1 block, 64 threads.
__global__ void gn_final() {
    int t = threadIdx.x;
    if (t < BB * NGROUP) {
        float s = 0.f, s2 = 0.f;
#pragma unroll
        for (int i = 0; i < NSLICE; i++) {
            s += g_gnp[(t * NSLICE + i) * 2];
            s2 += g_gnp[(t * NSLICE + i) * 2 + 1];
        }
        float mean = s / (float)(CPG * HWN);
        float var = s2 / (float)(CPG * HWN) - mean * mean;
        g_gnm[t * 2] = mean;
        g_gnm[t * 2 + 1] = rsqrtf(var + EPSV);
    }
}

// Phase 3: apply + transpose to (b,n,c) fp16. grid (NSLICE, NGROUP, BB).
__global__ void gn_apply(const float* __restrict__ x,
                         const float* __restrict__ gamma,
                         const float* __restrict__ beta) {
    const int s = blockIdx.x, g = blockIdx.y, b = blockIdx.z;
    const int c0 = g * CPG;
    const int tid = threadIdx.x;
    __shared__ float sg[CPG], sbt[CPG];
    __shared__ float smean, sinv;
    if (tid < CPG) { sg[tid] = gamma[c0 + tid]; sbt[tid] = beta[c0 + tid]; }
    if (tid == 0) {
        smean = g_gnm[(b * NGROUP + g) * 2];
        sinv = g_gnm[(b * NGROUP + g) * 2 + 1];
    }
    __syncthreads();
    const float mean = smean, inv = sinv;
    const float* xc = x + ((size_t)b * CC + c0) * HWN;
#pragma unroll 2
    for (int pp = tid; pp < SLPX; pp += 256) {
        const int p = s * SLPX + pp;
        half_t hh[CPG];
#pragma unroll
        for (int i = 0; i < CPG; i++) {
            float v = xc[(size_t)i * HWN + p];
            hh[i] = __float2half_rn((v - mean) * inv * sg[i] + sbt[i]);
        }
        size_t o = ((size_t)b * HWN + p) * CC + c0;
        *(uint4*)(g_t + o) = *(uint4*)(hh);
        *(uint4*)(g_t + o + 8) = *(uint4*)(hh + 8);
    }
}

// ---------------- per-row inverse sums of P (deterministic) ----------------
__global__ void rowsum_inv() {
    const size_t row = blockIdx.x;
    const __half2* p = (const __half2*)(g_p + row * HWN);
    const int tid = threadIdx.x;
    float s = 0.f;
#pragma unroll
    for (int i = 0; i < 8; i++) {
        float2 v = __half22float2(p[tid + i * 256]);
        s += v.x + v.y;
    }
    __shared__ float red[256];
    red[tid] = s;
    __syncthreads();
    for (int off = 128; off > 0; off >>= 1) {
        if (tid < off) red[tid] += red[tid + off];
        __syncthreads();
    }
    if (tid == 0) g_rsi[row] = 1.f / red[0];
}

// ---------------- host launch ----------------
extern "C" void kernel_launch(void* const* d_in, const int* in_sizes, int n_in,
                              void* d_out, int out_size) {
    const float* x     = (const float*)d_in[0];
    const float* gamma = (const float*)d_in[1];
    const float* beta  = (const float*)d_in[2];
    const float* wq    = (const float*)d_in[3];
    const float* bq    = (const float*)d_in[4];
    const float* wk    = (const float*)d_in[5];
    const float* bk    = (const float*)d_in[6];
    const float* wv    = (const float*)d_in[7];
    const float* bv    = (const float*)d_in[8];
    const float* wp    = (const float*)d_in[9];
    const float* bp    = (const float*)d_in[10];
    float* out = (float*)d_out;

    half_t *pt, *pwh, *pwph, *pq, *pk, *pvt, *pp, *pao;
    float *pbqkv, *prsi;
    cudaGetSymbolAddress((void**)&pt,   g_t);
    cudaGetSymbolAddress((void**)&pwh,  g_wh);
    cudaGetSymbolAddress((void**)&pwph, g_wph);
    cudaGetSymbolAddress((void**)&pbqkv, g_bqkv);
    cudaGetSymbolAddress((void**)&pq,   g_q);
    cudaGetSymbolAddress((void**)&pk,   g_k);
    cudaGetSymbolAddress((void**)&pvt,  g_vt);
    cudaGetSymbolAddress((void**)&pp,   g_p);
    cudaGetSymbolAddress((void**)&prsi, g_rsi);
    cudaGetSymbolAddress((void**)&pao,  g_ao);

    const int DSMEM = 3 * STG;  // 96KB
    cudaFuncSetAttribute(gemm_mma<4>, cudaFuncAttributeMaxDynamicSharedMemorySize, DSMEM);
    cudaFuncSetAttribute(gemm_mma<5>, cudaFuncAttributeMaxDynamicSharedMemorySize, DSMEM);
    cudaFuncSetAttribute(gemm_mma<6>, cudaFuncAttributeMaxDynamicSharedMemorySize, DSMEM);
    cudaFuncSetAttribute(gemm_mma<3>, cudaFuncAttributeMaxDynamicSharedMemorySize, DSMEM);

    const float scale = 0.044194173824159216f;         // 512^-0.5
    const float alphaS = scale * 1.4426950408889634f;  // fold log2(e) for exp2
    const long SQC = (long)HWN * CC;
    const long SQQ = (long)HWN * HWN;

    // 1) convert weights/bias + groupnorm (3-phase)
    convert_w<<<dim3(CC * CC / 256, 4), 256>>>(wq, wk, wv, wp, bq, bk, bv);
    gn_partial<<<dim3(NSLICE, NGROUP, BB), 256>>>(x);
    gn_final<<<1, 64>>>();
    gn_apply<<<dim3(NSLICE, NGROUP, BB), 256>>>(x, gamma, beta);

    // 2) fused QKV: N = 1536 over stacked weights
    {
        dim3 grid(3 * CC / Bb_N, BB * HWN / Bb_M, 1);
        gemm_mma<4><<<grid, 256, DSMEM>>>(pt, pwh, pbqkv,
                                          nullptr, pq, pk, pvt, nullptr,
                                          CC, CC, CC, CC, 0, 0, 0, 0.f);
    }

    // 3) P = exp2(Q K^T * scale * log2e)  (batched, fp16 out, fused exp)
    {
        dim3 grid(HWN / Bb_N, HWN / Bb_M, BB);
        gemm_mma<5><<<grid, 256, DSMEM>>>(pq, pk, nullptr,
                                          nullptr, pp, nullptr, nullptr, nullptr,
                                          CC, CC, CC, HWN, SQC, SQC, SQQ, alphaS);
    }

    // 4) per-row inverse sums
    rowsum_inv<<<BB * HWN, 256>>>();

    // 5) O = (P @ V) * inv_rowsum  (B = V^T)
    {
        dim3 grid(CC / Bb_N, HWN / Bb_M, BB);
        gemm_mma<6><<<grid, 256, DSMEM>>>(pp, pvt, nullptr,
                                          nullptr, pao, nullptr, nullptr, prsi,
                                          HWN, HWN, HWN, CC, SQQ, (long)CC * HWN, SQC, 0.f);
    }

    // 6) proj + bias + residual, transposed store to (b,c,h,w)
    {
        dim3 grid(CC / Bb_N, BB * HWN / Bb_M, 1);
        gemm_mma<3><<<grid, 256, DSMEM>>>(pao, pwph, bp,
                                          out, nullptr, nullptr, nullptr, x,
                                          CC, CC, CC, CC, 0, 0, 0, 0.f);
    }
}

// round 9
// speedup vs baseline: 9.5756x; 1.0332x over previous
#include <cuda_runtime.h>
#include <cuda_fp16.h>
#include <math.h>
#include <stdint.h>

#define BB 2
#define CC 512
#define HWN 4096
#define NGROUP 32
#define CPG 16
#define EPSV 1e-6f
#define NSLICE 8
#define SLPX (HWN / NSLICE)  // 512 px per slice
#define NCB (HWN / 128)      // 32 col-blocks for rowsum partials

typedef __half half_t;

// ---------------- scratch (static device globals; no allocs allowed) ----------------
__device__ half_t g_t  [(size_t)BB * HWN * CC];   // groupnormed (b,n,c) fp16
__device__ half_t g_wh [(size_t)3 * CC * CC];     // [wq;wk;wv] fp16, rows = out-ch
__device__ half_t g_wph[(size_t)CC * CC];         // wp fp16
__device__ float  g_bqkv[3 * CC];                 // [bq;bk;bv]
__device__ half_t g_q  [(size_t)BB * HWN * CC];   // Q fp16
__device__ half_t g_k  [(size_t)BB * HWN * CC];   // K fp16
__device__ half_t g_vt [(size_t)BB * CC * HWN];   // V^T fp16 (b,c,n)
__device__ half_t g_p  [(size_t)BB * HWN * HWN];  // unnormalized probs fp16
__device__ float  g_rsp[(size_t)BB * NCB * HWN];  // rowsum partials per col-block
__device__ half_t g_ao [(size_t)BB * HWN * CC];   // attn@V fp16
__device__ float  g_gnp[BB * NGROUP * NSLICE * 2]; // groupnorm partial sums
__device__ float  g_gnm[BB * NGROUP * 2];          // mean, inv per group

// ================= helpers =================
__device__ __forceinline__ uint32_t smem_u32(const void* p) {
    uint32_t a;
    asm("{ .reg .u64 t; cvta.to.shared.u64 t, %1; cvt.u32.u64 %0, t; }" : "=r"(a) : "l"(p));
    return a;
}
#define CP16(dst, src) \
    asm volatile("cp.async.cg.shared.global [%0], [%1], 16;" :: "r"(dst), "l"(src))
#define CP_COMMIT() asm volatile("cp.async.commit_group;" ::: "memory")
#define CP_WAIT1()  asm volatile("cp.async.wait_group 1;" ::: "memory")

#define LDSM4(r, addr) \
    asm volatile("ldmatrix.sync.aligned.m8n8.x4.shared.b16 {%0,%1,%2,%3}, [%4];" \
        : "=r"((r)[0]), "=r"((r)[1]), "=r"((r)[2]), "=r"((r)[3]) : "r"(addr))

#define MMA_F16(d, a, b) \
    asm volatile("mma.sync.aligned.m16n8k16.row.col.f32.f16.f16.f32 " \
        "{%0,%1,%2,%3}, {%4,%5,%6,%7}, {%8,%9}, {%0,%1,%2,%3};" \
        : "+f"((d)[0]), "+f"((d)[1]), "+f"((d)[2]), "+f"((d)[3]) \
        : "r"((a)[0]), "r"((a)[1]), "r"((a)[2]), "r"((a)[3]), "r"((b)[0]), "r"((b)[1]))

// ================= single-fp16 HMMA GEMM (fp32 accum), 2 CTAs/SM =================
// C[m,n] = sum_k A[m,k]*B[n,k] (TN), A and B fp16 row-major [*,K].
// MODE 3: fp32 transposed out + bias + residual (final output)
// MODE 4: fused QKV routing: n<512 -> q; <1024 -> k; else v^T (transposed)
// MODE 5: P = exp2(acc * alpha) fp16 + per-tile rowsum partials -> g_rsp
// MODE 6: out = acc * inv_rowsum (reduced from g_rsp in prologue), fp16 store
#define Bb_M 128
#define Bb_N 128
#define Bb_K 64
#define STG 32768  // bytes per smem stage (A, B : 16KB each)

template <int MODE>
__global__ void __launch_bounds__(256, 2)
gemm_mma(const half_t* __restrict__ A, const half_t* __restrict__ B,
         const float* __restrict__ bias,
         float* __restrict__ Cf, half_t* __restrict__ Ch,
         half_t* __restrict__ C2, half_t* __restrict__ C3,
         const float* __restrict__ extra,
         int K, int lda, int ldb, int ldc,
         long sA, long sB, long sC, float alpha) {
    extern __shared__ __align__(1024) char smem[];
    const uint32_t sb32 = smem_u32(smem);
    const int tid = threadIdx.x;
    const int lane = tid & 31;
    const int wid = tid >> 5;
    const int wm = wid >> 2;
    const int wn = wid & 3;
    const long zz = blockIdx.z;

    A += zz * sA;
    B += zz * sB;

    const int bm = blockIdx.y * Bb_M;
    const int bn = blockIdx.x * Bb_N;
    const int nck = K / Bb_K;

    __shared__ float s_red[128][4];  // MODE 5: cross-warp rowsum partials
    __shared__ float s_inv[128];     // MODE 6: per-row inverse sums

    // MODE 6 prologue: reduce rowsum partials for this CTA's 128 rows
    if (MODE == 6) {
        if (tid < 128) {
            const float* rp = extra + (size_t)zz * NCB * HWN + bm + tid;
            float s = 0.f;
#pragma unroll
            for (int i = 0; i < NCB; i++) s += rp[(size_t)i * HWN];
            s_inv[tid] = 1.f / s;
        }
    }

    auto issue = [&](int ck) {
        const int st = ck % 3;
        const int k0 = ck * Bb_K;
        const uint32_t sbase = sb32 + st * STG;
#pragma unroll
        for (int p = 0; p < 4; p++) {
            int idx = tid + p * 256;
            int r = idx >> 3;
            int c8 = idx & 7;
            uint32_t d = (uint32_t)(r * 128) + (uint32_t)((c8 * 16) ^ ((r & 7) << 4));
            CP16(sbase + d,         A + (size_t)(bm + r) * lda + k0 + c8 * 8);
            CP16(sbase + 16384 + d, B + (size_t)(bn + r) * ldb + k0 + c8 * 8);
        }
        CP_COMMIT();
    };

    issue(0);
    issue(1);

    float acc[16][4];
#pragma unroll
    for (int i = 0; i < 16; i++)
#pragma unroll
        for (int j = 0; j < 4; j++) acc[i][j] = 0.f;

    const int arow = wm * 64 + (lane & 7) + (lane & 8);
    const uint32_t akx = ((lane >> 4) & 1) ? 16u : 0u;
    const int brow = wn * 32 + (lane & 7) + ((lane >> 4) & 1) * 8;
    const uint32_t bkx = (lane & 8) ? 16u : 0u;
    const uint32_t lxor = (uint32_t)((lane & 7) << 4);

    for (int ck = 0; ck < nck; ck++) {
        CP_WAIT1();
        __syncthreads();
        if (ck + 2 < nck) issue(ck + 2);
        else CP_COMMIT();
        const uint32_t ab = sb32 + (uint32_t)((ck % 3) * STG);

#pragma unroll
        for (int kk = 0; kk < 4; kk++) {
            const uint32_t kb = (uint32_t)(kk * 32);
            uint32_t fa[4][4], fb[4][2];
#pragma unroll
            for (int mf = 0; mf < 4; mf++) {
                uint32_t ad = ab + (uint32_t)((arow + mf * 16) * 128) + ((kb + akx) ^ lxor);
                LDSM4(fa[mf], ad);
            }
#pragma unroll
            for (int nfp = 0; nfp < 2; nfp++) {
                uint32_t bd = ab + 16384 + (uint32_t)((brow + nfp * 16) * 128) + ((kb + bkx) ^ lxor);
                uint32_t t[4];
                LDSM4(t, bd);
                fb[nfp * 2][0] = t[0]; fb[nfp * 2][1] = t[1];
                fb[nfp * 2 + 1][0] = t[2]; fb[nfp * 2 + 1][1] = t[3];
            }
#pragma unroll
            for (int mf = 0; mf < 4; mf++)
#pragma unroll
                for (int nf = 0; nf < 4; nf++)
                    MMA_F16(acc[mf * 4 + nf], fa[mf], fb[nf]);
        }
    }

    // ---------------- epilogue ----------------
    if (MODE == 5 || MODE == 6) Ch += zz * sC;

    float rsum[8];
    if (MODE == 5) {
#pragma unroll
        for (int i = 0; i < 8; i++) rsum[i] = 0.f;
    }

#pragma unroll
    for (int mf = 0; mf < 4; mf++) {
#pragma unroll
        for (int nf = 0; nf < 4; nf++) {
            float* c = acc[mf * 4 + nf];
            const int m0 = bm + wm * 64 + mf * 16 + (lane >> 2);
            const int n0 = bn + wn * 32 + nf * 8 + 2 * (lane & 3);
#pragma unroll
            for (int hf = 0; hf < 2; hf++) {
                const int m = m0 + hf * 8;
                float v0 = c[hf * 2 + 0];
                float v1 = c[hf * 2 + 1];
                if (MODE == 5) {
                    __half2 xh = __floats2half2_rn(v0 * alpha, v1 * alpha);
                    __half2 ph = h2exp2(xh);
                    *(__half2*)(Ch + (size_t)m * ldc + n0) = ph;
                    float2 pf = __half22float2(ph);
                    rsum[mf * 2 + hf] += pf.x + pf.y;
                } else if (MODE == 6) {
                    float inv = s_inv[m - bm];
                    *(__half2*)(Ch + (size_t)m * ldc + n0) =
                        __floats2half2_rn(v0 * inv, v1 * inv);
                } else if (MODE == 4) {
                    v0 += bias[n0]; v1 += bias[n0 + 1];
                    const int seg = n0 >> 9;
                    const int nn = n0 & 511;
                    if (seg == 0) {
                        *(__half2*)(Ch + (size_t)m * CC + nn) = __floats2half2_rn(v0, v1);
                    } else if (seg == 1) {
                        *(__half2*)(C2 + (size_t)m * CC + nn) = __floats2half2_rn(v0, v1);
                    } else {
                        const int bb = m >> 12;
                        const int tok = m & (HWN - 1);
                        size_t o = ((size_t)bb * CC + nn) * HWN + tok;
                        C3[o] = __float2half_rn(v0);
                        C3[o + HWN] = __float2half_rn(v1);
                    }
                } else {  // MODE 3: proj + bias + residual, transposed fp32
                    const int bb = m >> 12;
                    const int tok = m & (HWN - 1);
                    size_t o = ((size_t)bb * CC + n0) * HWN + tok;
                    Cf[o] = v0 + bias[n0] + extra[o];
                    Cf[o + HWN] = v1 + bias[n0 + 1] + extra[o + HWN];
                }
            }
        }
    }

    // MODE 5: finish per-row sums for this 128x128 tile -> g_rsp
    if (MODE == 5) {
#pragma unroll
        for (int i = 0; i < 8; i++) {
            rsum[i] += __shfl_xor_sync(0xFFFFFFFFu, rsum[i], 1);
            rsum[i] += __shfl_xor_sync(0xFFFFFFFFu, rsum[i], 2);
        }
        __syncthreads();  // mainloop smem reads done; safe to reuse barriers
        if ((lane & 3) == 0) {
#pragma unroll
            for (int mf = 0; mf < 4; mf++)
#pragma unroll
                for (int hf = 0; hf < 2; hf++) {
                    int r = wm * 64 + mf * 16 + hf * 8 + (lane >> 2);
                    s_red[r][wn] = rsum[mf * 2 + hf];
                }
        }
        __syncthreads();
        if (tid < 128) {
            float s = s_red[tid][0] + s_red[tid][1] + s_red[tid][2] + s_red[tid][3];
            g_rsp[((size_t)zz * NCB + blockIdx.x) * HWN + bm + tid] = s;
        }
    }
}

// ---------------- weights fp32 -> fp16; bias concat ----------------
__global__ void convert_w(const float* __restrict__ w0, const float* __restrict__ w1,
                          const float* __restrict__ w2, const float* __restrict__ w3,
                          const float* __restrict__ b0, const float* __restrict__ b1,
                          const float* __restrict__ b2) {
    int i = blockIdx.x * 256 + threadIdx.x;
    int y = blockIdx.y;
    if (y < 3) {
        const float* w = (y == 0) ? w0 : (y == 1) ? w1 : w2;
        g_wh[(size_t)y * (CC * CC) + i] = __float2half_rn(w[i]);
        if (blockIdx.x < 2) {
            int j = blockIdx.x * 256 + threadIdx.x;
            const float* b = (y == 0) ? b0 : (y == 1) ? b1 : b2;
            g_bqkv[y * CC + j] = b[j];
        }
    } else {
        g_wph[i] = __float2half_rn(w3[i]);
    }
}

// ---------------- GroupNorm, 3-phase for full-chip occupancy ----------------
// Phase 1: partial sums per (b, group, slice). grid (NSLICE, NGROUP, BB).
__global__ void gn_partial(const float* __restrict__ x) {
    const int s = blockIdx.x, g = blockIdx.y, b = blockIdx.z;
    const int tid = threadIdx.x;
    const float* xc = x + ((size_t)b * CC + g * CPG) * HWN + s * SLPX;
    float sum = 0.f, sum2 = 0.f;
    // CPG rows x 128 float4 per row = 2048 float4; 256 threads -> 8 each
#pragma unroll
    for (int i = tid; i < CPG * (SLPX / 4); i += 256) {
        int row = i >> 7;
        int col = i & 127;
        float4 v = ((const float4*)(xc + (size_t)row * HWN))[col];
        sum += v.x + v.y + v.z + v.w;
        sum2 += v.x * v.x + v.y * v.y + v.z * v.z + v.w * v.w;
    }
    __shared__ float rs[256], rs2[256];
    rs[tid] = sum; rs2[tid] = sum2;
    __syncthreads();
    for (int off = 128; off > 0; off >>= 1) {
        if (tid < off) { rs[tid] += rs[tid + off]; rs2[tid] += rs2[tid + off]; }
        __syncthreads();
    }
    if (tid == 0) {
        int o = ((b * NGROUP + g) * NSLICE + s) * 2;
        g_gnp[o] = rs[0];
        g_gnp[o + 1] = rs2[0];
    }
}

// Phase 2: finalize mean/inv per (b, group). 1 block, 64 threads.
__global__ void gn_final() {
    int t = threadIdx.x;
    if (t < BB * NGROUP) {
        float s = 0.f, s2 = 0.f;
#pragma unroll
        for (int i = 0; i < NSLICE; i++) {
            s += g_gnp[(t * NSLICE + i) * 2];
            s2 += g_gnp[(t * NSLICE + i) * 2 + 1];
        }
        float mean = s / (float)(CPG * HWN);
        float var = s2 / (float)(CPG * HWN) - mean * mean;
        g_gnm[t * 2] = mean;
        g_gnm[t * 2 + 1] = rsqrtf(var + EPSV);
    }
}

// Phase 3: apply + transpose to (b,n,c) fp16. grid (NSLICE, NGROUP, BB).
__global__ void gn_apply(const float* __restrict__ x,
                         const float* __restrict__ gamma,
                         const float* __restrict__ beta) {
    const int s = blockIdx.x, g = blockIdx.y, b = blockIdx.z;
    const int c0 = g * CPG;
    const int tid = threadIdx.x;
    __shared__ float sg[CPG], sbt[CPG];
    __shared__ float smean, sinv;
    if (tid < CPG) { sg[tid] = gamma[c0 + tid]; sbt[tid] = beta[c0 + tid]; }
    if (tid == 0) {
        smean = g_gnm[(b * NGROUP + g) * 2];
        sinv = g_gnm[(b * NGROUP + g) * 2 + 1];
    }
    __syncthreads();
    const float mean = smean, inv = sinv;
    const float* xc = x + ((size_t)b * CC + c0) * HWN;
#pragma unroll 2
    for (int pp = tid; pp < SLPX; pp += 256) {
        const int p = s * SLPX + pp;
        half_t hh[CPG];
#pragma unroll
        for (int i = 0; i < CPG; i++) {
            float v = xc[(size_t)i * HWN + p];
            hh[i] = __float2half_rn((v - mean) * inv * sg[i] + sbt[i]);
        }
        size_t o = ((size_t)b * HWN + p) * CC + c0;
        *(uint4*)(g_t + o) = *(uint4*)(hh);
        *(uint4*)(g_t + o + 8) = *(uint4*)(hh + 8);
    }
}

// ---------------- host launch ----------------
extern "C" void kernel_launch(void* const* d_in, const int* in_sizes, int n_in,
                              void* d_out, int out_size) {
    const float* x     = (const float*)d_in[0];
    const float* gamma = (const float*)d_in[1];
    const float* beta  = (const float*)d_in[2];
    const float* wq    = (const float*)d_in[3];
    const float* bq    = (const float*)d_in[4];
    const float* wk    = (const float*)d_in[5];
    const float* bk    = (const float*)d_in[6];
    const float* wv    = (const float*)d_in[7];
    const float* bv    = (const float*)d_in[8];
    const float* wp    = (const float*)d_in[9];
    const float* bp    = (const float*)d_in[10];
    float* out = (float*)d_out;

    half_t *pt, *pwh, *pwph, *pq, *pk, *pvt, *pp, *pao;
    float *pbqkv, *prsp;
    cudaGetSymbolAddress((void**)&pt,   g_t);
    cudaGetSymbolAddress((void**)&pwh,  g_wh);
    cudaGetSymbolAddress((void**)&pwph, g_wph);
    cudaGetSymbolAddress((void**)&pbqkv, g_bqkv);
    cudaGetSymbolAddress((void**)&pq,   g_q);
    cudaGetSymbolAddress((void**)&pk,   g_k);
    cudaGetSymbolAddress((void**)&pvt,  g_vt);
    cudaGetSymbolAddress((void**)&pp,   g_p);
    cudaGetSymbolAddress((void**)&prsp, g_rsp);
    cudaGetSymbolAddress((void**)&pao,  g_ao);

    const int DSMEM = 3 * STG;  // 96KB
    cudaFuncSetAttribute(gemm_mma<4>, cudaFuncAttributeMaxDynamicSharedMemorySize, DSMEM);
    cudaFuncSetAttribute(gemm_mma<5>, cudaFuncAttributeMaxDynamicSharedMemorySize, DSMEM);
    cudaFuncSetAttribute(gemm_mma<6>, cudaFuncAttributeMaxDynamicSharedMemorySize, DSMEM);
    cudaFuncSetAttribute(gemm_mma<3>, cudaFuncAttributeMaxDynamicSharedMemorySize, DSMEM);

    const float scale = 0.044194173824159216f;         // 512^-0.5
    const float alphaS = scale * 1.4426950408889634f;  // fold log2(e) for exp2
    const long SQC = (long)HWN * CC;
    const long SQQ = (long)HWN * HWN;

    // 1) convert weights/bias + groupnorm (3-phase)
    convert_w<<<dim3(CC * CC / 256, 4), 256>>>(wq, wk, wv, wp, bq, bk, bv);
    gn_partial<<<dim3(NSLICE, NGROUP, BB), 256>>>(x);
    gn_final<<<1, 64>>>();
    gn_apply<<<dim3(NSLICE, NGROUP, BB), 256>>>(x, gamma, beta);

    // 2) fused QKV: N = 1536 over stacked weights
    {
        dim3 grid(3 * CC / Bb_N, BB * HWN / Bb_M, 1);
        gemm_mma<4><<<grid, 256, DSMEM>>>(pt, pwh, pbqkv,
                                          nullptr, pq, pk, pvt, nullptr,
                                          CC, CC, CC, CC, 0, 0, 0, 0.f);
    }

    // 3) P = exp2(Q K^T * scale * log2e) + rowsum partials (fused)
    {
        dim3 grid(HWN / Bb_N, HWN / Bb_M, BB);
        gemm_mma<5><<<grid, 256, DSMEM>>>(pq, pk, nullptr,
                                          nullptr, pp, nullptr, nullptr, nullptr,
                                          CC, CC, CC, HWN, SQC, SQC, SQQ, alphaS);
    }

    // 4) O = (P @ V) * inv_rowsum  (inv reduced from partials in prologue)
    {
        dim3 grid(CC / Bb_N, HWN / Bb_M, BB);
        gemm_mma<6><<<grid, 256, DSMEM>>>(pp, pvt, nullptr,
                                          nullptr, pao, nullptr, nullptr, prsp,
                                          HWN, HWN, HWN, CC, SQQ, (long)CC * HWN, SQC, 0.f);
    }

    // 5) proj + bias + residual, transposed store to (b,c,h,w)
    {
        dim3 grid(CC / Bb_N, BB * HWN / Bb_M, 1);
        gemm_mma<3><<<grid, 256, DSMEM>>>(pao, pwph, bp,
                                          out, nullptr, nullptr, nullptr, x,
                                          CC, CC, CC, CC, 0, 0, 0, 0.f);
    }
}